// round 1
// baseline (speedup 1.0000x reference)
#include <cuda_runtime.h>
#include <math.h>

#define NN 100000
#define EE 200000
#define AA 400000
#define DD 128
#define LL 5
#define KB 240   // bond rbf K (8 features x 30 centers)
#define KAP 40   // angle A stride (37 used)

// ---------------- scratch (static device globals; no runtime alloc) ----------
__device__ float g_h[NN*DD];
__device__ float g_hb[EE*DD];
__device__ float g_pre[EE*DD];
__device__ float g_t[EE*DD];
__device__ float g_embB[EE*DD];
__device__ float g_ang[AA*DD];
__device__ float g_Abond[EE*KB];
__device__ float g_Aang[AA*KAP];
__device__ float g_Wang[LL*37*DD];
__device__ float g_bang[LL*DD];
__device__ float g_bbond[(LL+1)*DD];
__device__ float g_stats[256];
__device__ float g_bns[DD];
__device__ float g_bnsh[DD];
__device__ float g_obs[DD];
__device__ float g_obsh[DD];

__constant__ double c_bf_start[8] = {0.0,0.0,3.0,0.0,0.0,0.0,0.0,0.0};
__constant__ double c_bf_step[8]  = {0.1,0.05,0.3,0.05,0.05,0.05,0.5,0.05};
__constant__ int    c_bf_cnt[8]   = {20,20,30,20,20,20,20,20};
__constant__ float  c_bf_g[8]     = {10.f,1.f,1.f,1.f,1.f,1.f,2.f,1.f};

// ---------------- generic tiled fp32 GEMM: Y[M,128] = A[M,K] @ W[K,128] + bias
// optional: TRANSFORM (relu(bn()) applied to A on load), STATS (col sum/sumsq
// accumulated into stats[256]), ACCUM (Y += result).
template<bool TRANSFORM, bool STATS, bool ACCUM>
__global__ void __launch_bounds__(256,2) gemm_tile(
    const float* __restrict__ Ain, int lda, int K,
    const float* __restrict__ Wg, const float* __restrict__ bias,
    float* __restrict__ Y, int M,
    const float* __restrict__ sc, const float* __restrict__ sh,
    float* __restrict__ stats)
{
    __shared__ float Xs[128][33];
    __shared__ float Ws[32][128];
    const int tid = threadIdx.x;
    const int tx = tid & 15;
    const int ty = tid >> 4;
    const int m0 = blockIdx.x << 7;

    float acc[8][8];
#pragma unroll
    for (int i=0;i<8;++i)
#pragma unroll
        for (int j=0;j<8;++j) acc[i][j] = 0.f;

    const int nk = (K + 31) >> 5;
    for (int kc = 0; kc < nk; ++kc) {
        const int kb = kc << 5;
#pragma unroll
        for (int t = 0; t < 16; ++t) {
            int e = (t<<8) + tid;
            int r = e >> 5, k = e & 31;
            int gk = kb + k;
            int row = m0 + r;
            float v = 0.f;
            if (row < M && gk < K) {
                v = Ain[row*lda + gk];
                if (TRANSFORM) v = fmaxf(fmaf(v, __ldg(&sc[gk]), __ldg(&sh[gk])), 0.f);
            }
            Xs[r][k] = v;
        }
#pragma unroll
        for (int t = 0; t < 16; ++t) {
            int e = (t<<8) + tid;
            int k = e >> 7, c = e & 127;
            int gk = kb + k;
            Ws[k][c] = (gk < K) ? Wg[gk*128 + c] : 0.f;
        }
        __syncthreads();
#pragma unroll
        for (int k = 0; k < 32; ++k) {
            float xv[8], wv[8];
#pragma unroll
            for (int i=0;i<8;++i) xv[i] = Xs[ty + (i<<4)][k];
#pragma unroll
            for (int j=0;j<8;++j) wv[j] = Ws[k][tx + (j<<4)];
#pragma unroll
            for (int i=0;i<8;++i)
#pragma unroll
                for (int j=0;j<8;++j) acc[i][j] = fmaf(xv[i], wv[j], acc[i][j]);
        }
        __syncthreads();
    }

    float bv[8];
#pragma unroll
    for (int j=0;j<8;++j) bv[j] = bias[tx + (j<<4)];

    float cs[8], cq[8];
#pragma unroll
    for (int j=0;j<8;++j){ cs[j]=0.f; cq[j]=0.f; }

#pragma unroll
    for (int i=0;i<8;++i) {
        int row = m0 + ty + (i<<4);
        if (row < M) {
#pragma unroll
            for (int j=0;j<8;++j) {
                int c = tx + (j<<4);
                float y = acc[i][j] + bv[j];
                if (ACCUM) y += Y[row*128 + c];
                Y[row*128 + c] = y;
                if (STATS) { cs[j] += y; cq[j] += y*y; }
            }
        }
    }

    if (STATS) {
        __syncthreads();
        float* sS = &Xs[0][0];
        float* sQ = &Ws[0][0];
#pragma unroll
        for (int j=0;j<8;++j) {
            int c = tx + (j<<4);
            sS[ty*128 + c] = cs[j];
            sQ[ty*128 + c] = cq[j];
        }
        __syncthreads();
        if (tid < 128) {
            float s=0.f, q=0.f;
#pragma unroll
            for (int r=0;r<16;++r){ s += sS[r*128+tid]; q += sQ[r*128+tid]; }
            atomicAdd(&stats[tid], s);
            atomicAdd(&stats[128+tid], q);
        }
    }
}

// ---------------- GIN helpers -----------------------------------------------
__global__ void k_init_pre(const float4* __restrict__ X, float4* __restrict__ P,
                           int M32, const float* __restrict__ epsP,
                           float* __restrict__ stats)
{
    int t = blockIdx.x*blockDim.x + threadIdx.x;
    if (t < 256) stats[t] = 0.f;
    if (t >= M32) return;
    float e = 1.f + *epsP;
    float4 x = X[t];
    x.x *= e; x.y *= e; x.z *= e; x.w *= e;
    P[t] = x;
}

__global__ void k_scatter(const float4* __restrict__ X, const float4* __restrict__ EA,
                          const int* __restrict__ src, const int* __restrict__ dst,
                          float4* __restrict__ P, int E32)
{
    int t = blockIdx.x*blockDim.x + threadIdx.x;
    if (t >= E32) return;
    int e = t >> 5, l = t & 31;
    int s = src[e], d = dst[e];
    float4 x = X[s*32 + l];
    float4 a = EA[(e<<5) + l];
    float4 m;
    m.x = fmaxf(x.x + a.x, 0.f);
    m.y = fmaxf(x.y + a.y, 0.f);
    m.z = fmaxf(x.z + a.z, 0.f);
    m.w = fmaxf(x.w + a.w, 0.f);
#if defined(__CUDA_ARCH__) && (__CUDA_ARCH__ >= 900)
    atomicAdd(&P[d*32 + l], m);
#else
    float* p = (float*)&P[d*32 + l];
    atomicAdd(p+0, m.x); atomicAdd(p+1, m.y);
    atomicAdd(p+2, m.z); atomicAdd(p+3, m.w);
#endif
}

__global__ void k_bn_finalize(float* __restrict__ stats, const float* __restrict__ g,
                              const float* __restrict__ b, float invM,
                              float* __restrict__ oscale, float* __restrict__ oshift)
{
    int c = threadIdx.x;   // 128
    float mu  = stats[c] * invM;
    float var = stats[128+c] * invM - mu*mu;
    float rs  = rsqrtf(var + 1e-5f);
    float scv = g[c] * rs;
    oscale[c] = scv;
    oshift[c] = b[c] - mu*scv;
    stats[c] = 0.f;
    stats[128+c] = 0.f;
}

__global__ void k_bnrelu(float4* __restrict__ X, int M32,
                         const float* __restrict__ sc, const float* __restrict__ sh)
{
    int t = blockIdx.x*blockDim.x + threadIdx.x;
    if (t >= M32) return;
    int cb = (t & 31) << 2;
    float4 v = X[t];
    v.x = fmaxf(fmaf(v.x, sc[cb+0], sh[cb+0]), 0.f);
    v.y = fmaxf(fmaf(v.y, sc[cb+1], sh[cb+1]), 0.f);
    v.z = fmaxf(fmaf(v.z, sc[cb+2], sh[cb+2]), 0.f);
    v.w = fmaxf(fmaf(v.w, sc[cb+3], sh[cb+3]), 0.f);
    X[t] = v;
}

// ---------------- embeddings ------------------------------------------------
__global__ void k_atom_embed(const int* __restrict__ xa, const float4* __restrict__ tab,
                             float4* __restrict__ H, int N32)
{
    int t = blockIdx.x*blockDim.x + threadIdx.x;
    if (t >= N32) return;
    int n = t >> 5, l = t & 31;
    float4 s = make_float4(0.f,0.f,0.f,0.f);
#pragma unroll
    for (int f=0; f<9; ++f) {
        int idx = xa[n*9 + f];
        float4 v = tab[(f*124 + idx)*32 + l];
        s.x += v.x; s.y += v.y; s.z += v.z; s.w += v.w;
    }
    H[t] = s;
}

__global__ void k_bond_int_embed(const int* __restrict__ ei, const float4* __restrict__ tab,
                                 float4* __restrict__ O, int E32)
{
    int t = blockIdx.x*blockDim.x + threadIdx.x;
    if (t >= E32) return;
    int e = t >> 5, l = t & 31;
    float4 s = make_float4(0.f,0.f,0.f,0.f);
#pragma unroll
    for (int f=0; f<3; ++f) {
        int idx = ei[e*3 + f];
        float4 v = tab[(f*12 + idx)*32 + l];
        s.x += v.x; s.y += v.y; s.z += v.z; s.w += v.w;
    }
    O[t] = s;
}

// RBF basis matrices (layer-independent; computed once per launch)
__global__ void k_rbf_bond(const float* __restrict__ xf, float* __restrict__ Aout)
{
    int e = blockIdx.x;
    int k = threadIdx.x;          // [0,240)
    int f = k / 30, c = k % 30;
    float v = 0.f;
    if (c < c_bf_cnt[f]) {
        float x = xf[e*8 + f];
        float ctr = (float)(c_bf_start[f] + c_bf_step[f] * (double)c);
        float d = x - ctr;
        v = expf(-c_bf_g[f] * d * d);
    }
    Aout[e*KB + k] = v;
}

__global__ void k_rbf_ang(const float* __restrict__ xa, float* __restrict__ Aout, int A)
{
    int a = blockIdx.x*8 + threadIdx.x/40;
    int k = threadIdx.x % 40;
    if (a >= A) return;
    float v;
    if (k < 32) {
        float ctr = (float)((double)k * 0.1);
        float d = xa[a*6] - ctr;
        v = expf(-10.f * d * d);
    } else if (k < 37) {
        v = xa[a*6 + (k - 31)];
    } else {
        v = 0.f;
    }
    Aout[a*KAP + k] = v;
}

// pack angle weights [32+5,128] per layer and combined biases
__global__ void k_pack(const float* __restrict__ baWang, const float* __restrict__ baWrest,
                       const float* __restrict__ baBang, const float* __restrict__ baBrest,
                       const float* __restrict__ bfb,
                       float* __restrict__ Wang, float* __restrict__ bang,
                       float* __restrict__ bbond)
{
    int c = threadIdx.x;   // 128
    for (int l=0; l<LL; ++l) {
        for (int r=0; r<37; ++r) {
            float v = (r < 32) ? baWang[(l*32 + r)*128 + c]
                               : baWrest[(l*5 + (r-32))*128 + c];
            Wang[(l*37 + r)*128 + c] = v;
        }
        bang[l*128 + c] = baBang[l*128 + c] + baBrest[l*128 + c];
    }
    for (int l=0; l<=LL; ++l) {
        float s = 0.f;
        for (int f=0; f<8; ++f) s += bfb[(l*8 + f)*128 + c];
        bbond[l*128 + c] = s;
    }
}

__global__ void k_copy_out(const float4* __restrict__ H, const float4* __restrict__ HB,
                           float4* __restrict__ O, int N32, int T32)
{
    int t = blockIdx.x*blockDim.x + threadIdx.x;
    if (t >= T32) return;
    O[t] = (t < N32) ? H[t] : HB[t - N32];
}

// ---------------- launcher ---------------------------------------------------
extern "C" void kernel_launch(void* const* d_in, const int* in_sizes, int n_in,
                              void* d_out, int out_size)
{
    const int N = NN, E = EE, A = AA;

    const int*   x_atom      = (const int*)  d_in[0];
    const int*   edge_index  = (const int*)  d_in[1];
    const int*   eint        = (const int*)  d_in[2];
    const int*   eiba        = (const int*)  d_in[3];
    const float* eaf         = (const float*)d_in[4];
    const float* eab         = (const float*)d_in[5];
    const float* atom_tables = (const float*)d_in[6];
    const float* bond_tables = (const float*)d_in[7];
    const float* bf_W        = (const float*)d_in[8];
    const float* bf_b        = (const float*)d_in[9];
    const float* ba_W_ang    = (const float*)d_in[10];
    const float* ba_b_ang    = (const float*)d_in[11];
    const float* ba_W_rest   = (const float*)d_in[12];
    const float* ba_b_rest   = (const float*)d_in[13];
    const float* eps_a       = (const float*)d_in[14];
    const float* W1_a        = (const float*)d_in[15];
    const float* b1_a        = (const float*)d_in[16];
    const float* bng_a       = (const float*)d_in[17];
    const float* bnb_a       = (const float*)d_in[18];
    const float* W2_a        = (const float*)d_in[19];
    const float* b2_a        = (const float*)d_in[20];
    const float* eps_g       = (const float*)d_in[21];
    const float* W1_g        = (const float*)d_in[22];
    const float* b1_g        = (const float*)d_in[23];
    const float* bng_g       = (const float*)d_in[24];
    const float* bnb_g       = (const float*)d_in[25];
    const float* W2_g        = (const float*)d_in[26];
    const float* b2_g        = (const float*)d_in[27];
    const float* obng_a      = (const float*)d_in[28];
    const float* obnb_a      = (const float*)d_in[29];
    const float* obng_ba     = (const float*)d_in[30];
    const float* obnb_ba     = (const float*)d_in[31];

    const int* src  = edge_index;
    const int* dst  = edge_index + E;
    const int* srcb = eiba;
    const int* dstb = eiba + A;

    float *ph, *phb, *ppre, *pt, *pembB, *pang, *pAb, *pAa;
    float *pWang, *pbang, *pbbond, *pstats, *pbns, *pbnsh, *pobs, *pobsh;
    cudaGetSymbolAddress((void**)&ph,    g_h);
    cudaGetSymbolAddress((void**)&phb,   g_hb);
    cudaGetSymbolAddress((void**)&ppre,  g_pre);
    cudaGetSymbolAddress((void**)&pt,    g_t);
    cudaGetSymbolAddress((void**)&pembB, g_embB);
    cudaGetSymbolAddress((void**)&pang,  g_ang);
    cudaGetSymbolAddress((void**)&pAb,   g_Abond);
    cudaGetSymbolAddress((void**)&pAa,   g_Aang);
    cudaGetSymbolAddress((void**)&pWang, g_Wang);
    cudaGetSymbolAddress((void**)&pbang, g_bang);
    cudaGetSymbolAddress((void**)&pbbond,g_bbond);
    cudaGetSymbolAddress((void**)&pstats,g_stats);
    cudaGetSymbolAddress((void**)&pbns,  g_bns);
    cudaGetSymbolAddress((void**)&pbnsh, g_bnsh);
    cudaGetSymbolAddress((void**)&pobs,  g_obs);
    cudaGetSymbolAddress((void**)&pobsh, g_obsh);

    auto blks = [](int n){ return (n + 255) / 256; };

    // --- one-time (per call) precompute ---
    k_pack<<<1,128>>>(ba_W_ang, ba_W_rest, ba_b_ang, ba_b_rest, bf_b,
                      pWang, pbang, pbbond);
    k_rbf_bond<<<E, 240>>>(eaf, pAb);
    k_rbf_ang<<<(A + 7)/8, 320>>>(eab, pAa, A);

    // --- initial embeddings ---
    k_atom_embed<<<blks(N*32),256>>>(x_atom, (const float4*)atom_tables, (float4*)ph, N*32);
    k_bond_int_embed<<<blks(E*32),256>>>(eint, (const float4*)bond_tables, (float4*)phb, E*32);
    gemm_tile<false,false,true><<<(E+127)/128,256>>>(pAb, KB, KB, bf_W, pbbond,
                                                     phb, E, nullptr, nullptr, nullptr);

    for (int l = 0; l < LL; ++l) {
        const bool last = (l == LL - 1);

        // ===== atom GIN conv =====
        k_init_pre<<<blks(N*32),256>>>((const float4*)ph, (float4*)ppre, N*32, eps_a + l, pstats);
        k_scatter<<<blks(E*32),256>>>((const float4*)ph, (const float4*)phb, src, dst,
                                      (float4*)ppre, E*32);
        gemm_tile<false,true,false><<<(N+127)/128,256>>>(ppre, 128, 128,
            W1_a + l*16384, b1_a + l*128, pt, N, nullptr, nullptr, pstats);
        k_bn_finalize<<<1,128>>>(pstats, bng_a + l*128, bnb_a + l*128, 1.0f/N, pbns, pbnsh);
        if (!last) {
            gemm_tile<true,true,false><<<(N+127)/128,256>>>(pt, 128, 128,
                W2_a + l*16384, b2_a + l*128, ph, N, pbns, pbnsh, pstats);
            k_bn_finalize<<<1,128>>>(pstats, obng_a + l*128, obnb_a + l*128, 1.0f/N, pobs, pobsh);
            k_bnrelu<<<blks(N*32),256>>>((float4*)ph, N*32, pobs, pobsh);
        } else {
            gemm_tile<true,false,false><<<(N+127)/128,256>>>(pt, 128, 128,
                W2_a + l*16384, b2_a + l*128, ph, N, pbns, pbnsh, nullptr);
        }

        // ===== bond embeddings for layer l+1 =====
        k_bond_int_embed<<<blks(E*32),256>>>(eint,
            (const float4*)(bond_tables + (l+1)*3*12*128), (float4*)pembB, E*32);
        gemm_tile<false,false,true><<<(E+127)/128,256>>>(pAb, KB, KB,
            bf_W + (l+1)*KB*128, pbbond + (l+1)*128, pembB, E, nullptr, nullptr, nullptr);
        gemm_tile<false,false,false><<<(A+127)/128,256>>>(pAa, KAP, 37,
            pWang + l*37*128, pbang + l*128, pang, A, nullptr, nullptr, nullptr);

        // ===== bond GIN conv =====
        k_init_pre<<<blks(E*32),256>>>((const float4*)pembB, (float4*)ppre, E*32, eps_g + l, pstats);
        k_scatter<<<blks(A*32),256>>>((const float4*)pembB, (const float4*)pang, srcb, dstb,
                                      (float4*)ppre, A*32);
        gemm_tile<false,true,false><<<(E+127)/128,256>>>(ppre, 128, 128,
            W1_g + l*16384, b1_g + l*128, pt, E, nullptr, nullptr, pstats);
        k_bn_finalize<<<1,128>>>(pstats, bng_g + l*128, bnb_g + l*128, 1.0f/E, pbns, pbnsh);
        if (!last) {
            gemm_tile<true,true,false><<<(E+127)/128,256>>>(pt, 128, 128,
                W2_g + l*16384, b2_g + l*128, phb, E, pbns, pbnsh, pstats);
            k_bn_finalize<<<1,128>>>(pstats, obng_ba + l*128, obnb_ba + l*128, 1.0f/E, pobs, pobsh);
            k_bnrelu<<<blks(E*32),256>>>((float4*)phb, E*32, pobs, pobsh);
        } else {
            gemm_tile<true,false,false><<<(E+127)/128,256>>>(pt, 128, 128,
                W2_g + l*16384, b2_g + l*128, phb, E, pbns, pbnsh, nullptr);
        }
    }

    // --- output: [h (N*128) ; h_ba (E*128)] ---
    int T32 = (N + E) * 32;
    k_copy_out<<<blks(T32),256>>>((const float4*)ph, (const float4*)phb,
                                  (float4*)d_out, N*32, T32);
}

// round 3
// speedup vs baseline: 1.1384x; 1.1384x over previous
#include <cuda_runtime.h>
#include <cuda_bf16.h>
#include <math.h>

#define NN 100000
#define EE 200000
#define AA 400000
#define DD 128
#define LL 5
#define KB 240   // bond rbf K (8 features x 30 centers)
#define KAP 40   // angle A stride (37 used, zero padded)

// ---------------- scratch (static device globals; no runtime alloc) ----------
__device__ float g_h[NN*DD];
__device__ float g_hb[EE*DD];
__device__ float g_pre[EE*DD];
__device__ float g_t[EE*DD];
__device__ float g_embB[EE*DD];
__device__ float g_ang[AA*DD];
__device__ float g_Abond[EE*KB];
__device__ float g_Aang[AA*KAP];
__device__ float g_Wang[LL*KAP*DD];
__device__ float g_bang[LL*DD];
__device__ float g_bbond[(LL+1)*DD];
__device__ float g_stats[256];
__device__ float g_bns[DD];
__device__ float g_bnsh[DD];
__device__ float g_obs[DD];
__device__ float g_obsh[DD];

__constant__ double c_bf_start[8] = {0.0,0.0,3.0,0.0,0.0,0.0,0.0,0.0};
__constant__ double c_bf_step[8]  = {0.1,0.05,0.3,0.05,0.05,0.05,0.5,0.05};
__constant__ int    c_bf_cnt[8]   = {20,20,30,20,20,20,20,20};
__constant__ float  c_bf_g[8]     = {10.f,1.f,1.f,1.f,1.f,1.f,2.f,1.f};

// split x,y (consecutive-k pair) into packed bf16x2 hi and residual lo
__device__ __forceinline__ void split_pack(float x, float y, unsigned &hi, unsigned &lo)
{
    __nv_bfloat16 bx = __float2bfloat16_rn(x);
    __nv_bfloat16 by = __float2bfloat16_rn(y);
    float rx = x - __bfloat162float(bx);
    float ry = y - __bfloat162float(by);
    __nv_bfloat16 brx = __float2bfloat16_rn(rx);
    __nv_bfloat16 bry = __float2bfloat16_rn(ry);
    hi = ((unsigned)__bfloat16_as_ushort(by) << 16) | __bfloat16_as_ushort(bx);
    lo = ((unsigned)__bfloat16_as_ushort(bry) << 16) | __bfloat16_as_ushort(brx);
}

#define MMA_BF16(d, a0,a1,a2,a3, b0,b1) \
    asm volatile( \
        "mma.sync.aligned.m16n8k16.row.col.f32.bf16.bf16.f32 " \
        "{%0,%1,%2,%3}, {%4,%5,%6,%7}, {%8,%9}, {%0,%1,%2,%3};" \
        : "+f"(d[0]), "+f"(d[1]), "+f"(d[2]), "+f"(d[3]) \
        : "r"(a0), "r"(a1), "r"(a2), "r"(a3), "r"(b0), "r"(b1))

// ---------------- bf16x3 tensor-core GEMM: Y[M,128] = A[M,K] @ W[K,128] + bias
// fp32-equivalent accuracy via hi/lo bf16 split (3 MMAs per tile).
// TRANSFORM: relu(bn()) applied to A on load; STATS: col sum/sumsq into stats;
// ACCUM: Y += result.  Requires K % 4 == 0, lda % 4 == 0.
template<bool TRANSFORM, bool STATS, bool ACCUM>
__global__ void __launch_bounds__(256,1) gemm_mma(
    const float* __restrict__ Ain, int lda, int K,
    const float* __restrict__ Wg, const float* __restrict__ bias,
    float* __restrict__ Y, int M,
    const float* __restrict__ sc, const float* __restrict__ sh,
    float* __restrict__ stats)
{
    // fragment-native smem: A [mt(8)][s(2)][lane(32)][reg(4)], B [nt(16)][s(2)][lane(32)][reg(2)]
    __shared__ unsigned Ash[2048], Asl[2048];
    __shared__ unsigned Bsh[2048], Bsl[2048];
    __shared__ float sSum[128], sSq[128];

    const int tid  = threadIdx.x;
    const int lane = tid & 31;
    const int warp = tid >> 5;
    const int wm = warp >> 2;   // 0..1
    const int wn = warp & 3;    // 0..3
    const int m0 = blockIdx.x << 7;

    if (STATS && tid < 128) { sSum[tid] = 0.f; sSq[tid] = 0.f; }

    float acc[4][4][4];
#pragma unroll
    for (int i=0;i<4;++i)
#pragma unroll
        for (int j=0;j<4;++j)
#pragma unroll
            for (int r=0;r<4;++r) acc[i][j][r] = 0.f;

    const int nchunk = (K + 31) >> 5;
    for (int ch = 0; ch < nchunk; ++ch) {
        const int kb = ch << 5;
        if (ch) __syncthreads();

        // ---- stage A tile [128 rows x 32 k] ----
        {
            const int q  = tid & 7;           // k group: kk = 4q
            const int r0 = tid >> 3;          // row base 0..31
            const int gk = kb + (q << 2);
            const int s  = q >> 2;            // k16 step
            const int k16_0 = (q << 2) & 15;
            const int p0  = k16_0 >> 1;       // even pair index 0,2,4,6
            const int tig0 = p0 & 3;
            const int ph0  = p0 >> 2;
#pragma unroll
            for (int it = 0; it < 4; ++it) {
                int row  = r0 + (it << 5);
                int grow = m0 + row;
                float4 v = make_float4(0.f,0.f,0.f,0.f);
                if (grow < M && gk < K) {
                    v = *(const float4*)(Ain + (long)grow*lda + gk);
                    if (TRANSFORM) {
                        v.x = fmaxf(fmaf(v.x, sc[gk+0], sh[gk+0]), 0.f);
                        v.y = fmaxf(fmaf(v.y, sc[gk+1], sh[gk+1]), 0.f);
                        v.z = fmaxf(fmaf(v.z, sc[gk+2], sh[gk+2]), 0.f);
                        v.w = fmaxf(fmaf(v.w, sc[gk+3], sh[gk+3]), 0.f);
                    }
                }
                int mt   = row >> 4;
                int gid  = row & 7;
                int row8 = (row >> 3) & 1;
                int reg  = row8 | (ph0 << 1);
                int base = (((mt << 1) + s) << 5);
                unsigned h0, l0, h1, l1;
                split_pack(v.x, v.y, h0, l0);
                split_pack(v.z, v.w, h1, l1);
                int i0 = (base + (gid << 2) + tig0) * 4 + reg;
                int i1 = (base + (gid << 2) + tig0 + 1) * 4 + reg;
                Ash[i0] = h0; Asl[i0] = l0;
                Ash[i1] = h1; Asl[i1] = l1;
            }
        }
        // ---- stage B tile [32 k x 128 cols] ----
        {
            const int kp  = tid & 15;         // k pair: k = 2kp, 2kp+1
            const int cg0 = tid >> 4;         // col group base 0..15
            const int gk0 = kb + (kp << 1);
            const int s   = kp >> 3;
            const int p   = kp & 7;
            const int tig = p & 3;
            const int reg = p >> 2;
            const bool ok = (gk0 < K);
#pragma unroll
            for (int it = 0; it < 2; ++it) {
                int col = ((cg0 + (it << 4)) << 2);  // 0..124 step 4
                float4 v0 = make_float4(0.f,0.f,0.f,0.f);
                float4 v1 = v0;
                if (ok) {
                    v0 = *(const float4*)(Wg + (long)gk0*128 + col);
                    v1 = *(const float4*)(Wg + (long)(gk0+1)*128 + col);
                }
                const float e0[4] = {v0.x, v0.y, v0.z, v0.w};
                const float e1[4] = {v1.x, v1.y, v1.z, v1.w};
#pragma unroll
                for (int c = 0; c < 4; ++c) {
                    int cc  = col + c;
                    int nt  = cc >> 3;
                    int gid = cc & 7;
                    unsigned h, l;
                    split_pack(e0[c], e1[c], h, l);
                    int idx = ((((nt << 1) + s) << 5) + (gid << 2) + tig) * 2 + reg;
                    Bsh[idx] = h; Bsl[idx] = l;
                }
            }
        }
        __syncthreads();

        // ---- compute: 2 k16 steps, 4x4 mma tiles per warp, 3 products each ----
#pragma unroll
        for (int s = 0; s < 2; ++s) {
            unsigned bh[4][2], bl[4][2];
#pragma unroll
            for (int ni = 0; ni < 4; ++ni) {
                int base = (((((wn*4 + ni) << 1) + s) << 5) | lane) << 1;
                uint2 fh = *(const uint2*)&Bsh[base];
                uint2 fl = *(const uint2*)&Bsl[base];
                bh[ni][0]=fh.x; bh[ni][1]=fh.y;
                bl[ni][0]=fl.x; bl[ni][1]=fl.y;
            }
#pragma unroll
            for (int mi = 0; mi < 4; ++mi) {
                int base = (((((wm*4 + mi) << 1) + s) << 5) | lane) << 2;
                uint4 ah = *(const uint4*)&Ash[base];
                uint4 al = *(const uint4*)&Asl[base];
#pragma unroll
                for (int ni = 0; ni < 4; ++ni) {
                    MMA_BF16(acc[mi][ni], ah.x, ah.y, ah.z, ah.w, bh[ni][0], bh[ni][1]);
                    MMA_BF16(acc[mi][ni], ah.x, ah.y, ah.z, ah.w, bl[ni][0], bl[ni][1]);
                    MMA_BF16(acc[mi][ni], al.x, al.y, al.z, al.w, bh[ni][0], bh[ni][1]);
                }
            }
        }
    }

    // ---- epilogue ----
    const int colq = (lane & 3) << 1;   // 0,2,4,6
    float bv[4][2];
#pragma unroll
    for (int ni = 0; ni < 4; ++ni) {
        int c = wn*32 + ni*8 + colq;
        bv[ni][0] = bias[c];
        bv[ni][1] = bias[c+1];
    }

    float cs[4][2], cq[4][2];
#pragma unroll
    for (int ni=0;ni<4;++ni){ cs[ni][0]=cs[ni][1]=0.f; cq[ni][0]=cq[ni][1]=0.f; }

#pragma unroll
    for (int mi = 0; mi < 4; ++mi) {
#pragma unroll
        for (int half = 0; half < 2; ++half) {
            int row = m0 + wm*64 + mi*16 + (lane >> 2) + half*8;
            if (row < M) {
#pragma unroll
                for (int ni = 0; ni < 4; ++ni) {
                    int c = wn*32 + ni*8 + colq;
                    float y0 = acc[mi][ni][half*2+0] + bv[ni][0];
                    float y1 = acc[mi][ni][half*2+1] + bv[ni][1];
                    float* yp = Y + (long)row*128 + c;
                    if (ACCUM) { y0 += yp[0]; y1 += yp[1]; }
                    *(float2*)yp = make_float2(y0, y1);
                    if (STATS) {
                        cs[ni][0] += y0; cs[ni][1] += y1;
                        cq[ni][0] += y0*y0; cq[ni][1] += y1*y1;
                    }
                }
            }
        }
    }

    if (STATS) {
        __syncthreads();
#pragma unroll
        for (int ni = 0; ni < 4; ++ni) {
            int c = wn*32 + ni*8 + colq;
            atomicAdd(&sSum[c],   cs[ni][0]);
            atomicAdd(&sSum[c+1], cs[ni][1]);
            atomicAdd(&sSq[c],    cq[ni][0]);
            atomicAdd(&sSq[c+1],  cq[ni][1]);
        }
        __syncthreads();
        if (tid < 128) {
            atomicAdd(&stats[tid],     sSum[tid]);
            atomicAdd(&stats[128+tid], sSq[tid]);
        }
    }
}

// ---------------- GIN helpers -----------------------------------------------
__global__ void k_init_pre(const float4* __restrict__ X, float4* __restrict__ P,
                           int M32, const float* __restrict__ epsP,
                           float* __restrict__ stats)
{
    int t = blockIdx.x*blockDim.x + threadIdx.x;
    if (t < 256) stats[t] = 0.f;
    if (t >= M32) return;
    float e = 1.f + *epsP;
    float4 x = X[t];
    x.x *= e; x.y *= e; x.z *= e; x.w *= e;
    P[t] = x;
}

__global__ void k_scatter(const float4* __restrict__ X, const float4* __restrict__ EA,
                          const int* __restrict__ src, const int* __restrict__ dst,
                          float4* __restrict__ P, int E32)
{
    int t = blockIdx.x*blockDim.x + threadIdx.x;
    if (t >= E32) return;
    int e = t >> 5, l = t & 31;
    int s = src[e], d = dst[e];
    float4 x = X[s*32 + l];
    float4 a = EA[(e<<5) + l];
    float4 m;
    m.x = fmaxf(x.x + a.x, 0.f);
    m.y = fmaxf(x.y + a.y, 0.f);
    m.z = fmaxf(x.z + a.z, 0.f);
    m.w = fmaxf(x.w + a.w, 0.f);
#if defined(__CUDA_ARCH__) && (__CUDA_ARCH__ >= 900)
    atomicAdd(&P[d*32 + l], m);
#else
    float* p = (float*)&P[d*32 + l];
    atomicAdd(p+0, m.x); atomicAdd(p+1, m.y);
    atomicAdd(p+2, m.z); atomicAdd(p+3, m.w);
#endif
}

__global__ void k_bn_finalize(float* __restrict__ stats, const float* __restrict__ g,
                              const float* __restrict__ b, float invM,
                              float* __restrict__ oscale, float* __restrict__ oshift)
{
    int c = threadIdx.x;   // 128
    float mu  = stats[c] * invM;
    float var = stats[128+c] * invM - mu*mu;
    float rs  = rsqrtf(var + 1e-5f);
    float scv = g[c] * rs;
    oscale[c] = scv;
    oshift[c] = b[c] - mu*scv;
    stats[c] = 0.f;
    stats[128+c] = 0.f;
}

__global__ void k_bnrelu(float4* __restrict__ X, int M32,
                         const float* __restrict__ sc, const float* __restrict__ sh)
{
    int t = blockIdx.x*blockDim.x + threadIdx.x;
    if (t >= M32) return;
    int cb = (t & 31) << 2;
    float4 v = X[t];
    v.x = fmaxf(fmaf(v.x, sc[cb+0], sh[cb+0]), 0.f);
    v.y = fmaxf(fmaf(v.y, sc[cb+1], sh[cb+1]), 0.f);
    v.z = fmaxf(fmaf(v.z, sc[cb+2], sh[cb+2]), 0.f);
    v.w = fmaxf(fmaf(v.w, sc[cb+3], sh[cb+3]), 0.f);
    X[t] = v;
}

// ---------------- embeddings ------------------------------------------------
__global__ void k_atom_embed(const int* __restrict__ xa, const float4* __restrict__ tab,
                             float4* __restrict__ H, int N32)
{
    int t = blockIdx.x*blockDim.x + threadIdx.x;
    if (t >= N32) return;
    int n = t >> 5, l = t & 31;
    float4 s = make_float4(0.f,0.f,0.f,0.f);
#pragma unroll
    for (int f=0; f<9; ++f) {
        int idx = xa[n*9 + f];
        float4 v = tab[(f*124 + idx)*32 + l];
        s.x += v.x; s.y += v.y; s.z += v.z; s.w += v.w;
    }
    H[t] = s;
}

__global__ void k_bond_int_embed(const int* __restrict__ ei, const float4* __restrict__ tab,
                                 float4* __restrict__ O, int E32)
{
    int t = blockIdx.x*blockDim.x + threadIdx.x;
    if (t >= E32) return;
    int e = t >> 5, l = t & 31;
    float4 s = make_float4(0.f,0.f,0.f,0.f);
#pragma unroll
    for (int f=0; f<3; ++f) {
        int idx = ei[e*3 + f];
        float4 v = tab[(f*12 + idx)*32 + l];
        s.x += v.x; s.y += v.y; s.z += v.z; s.w += v.w;
    }
    O[t] = s;
}

// RBF basis matrices (layer-independent; computed once per launch)
__global__ void k_rbf_bond(const float* __restrict__ xf, float* __restrict__ Aout)
{
    int e = blockIdx.x;
    int k = threadIdx.x;          // [0,240)
    int f = k / 30, c = k % 30;
    float v = 0.f;
    if (c < c_bf_cnt[f]) {
        float x = xf[e*8 + f];
        float ctr = (float)(c_bf_start[f] + c_bf_step[f] * (double)c);
        float d = x - ctr;
        v = expf(-c_bf_g[f] * d * d);
    }
    Aout[e*KB + k] = v;
}

__global__ void k_rbf_ang(const float* __restrict__ xa, float* __restrict__ Aout, int A)
{
    int a = blockIdx.x*8 + threadIdx.x/40;
    int k = threadIdx.x % 40;
    if (a >= A) return;
    float v;
    if (k < 32) {
        float ctr = (float)((double)k * 0.1);
        float d = xa[a*6] - ctr;
        v = expf(-10.f * d * d);
    } else if (k < 37) {
        v = xa[a*6 + (k - 31)];
    } else {
        v = 0.f;
    }
    Aout[a*KAP + k] = v;
}

// pack angle weights [40,128] per layer (zero padded) and combined biases
__global__ void k_pack(const float* __restrict__ baWang, const float* __restrict__ baWrest,
                       const float* __restrict__ baBang, const float* __restrict__ baBrest,
                       const float* __restrict__ bfb,
                       float* __restrict__ Wang, float* __restrict__ bang,
                       float* __restrict__ bbond)
{
    int c = threadIdx.x;   // 128
    for (int l=0; l<LL; ++l) {
        for (int r=0; r<KAP; ++r) {
            float v = 0.f;
            if (r < 32)      v = baWang[(l*32 + r)*128 + c];
            else if (r < 37) v = baWrest[(l*5 + (r-32))*128 + c];
            Wang[(l*KAP + r)*128 + c] = v;
        }
        bang[l*128 + c] = baBang[l*128 + c] + baBrest[l*128 + c];
    }
    for (int l=0; l<=LL; ++l) {
        float s = 0.f;
        for (int f=0; f<8; ++f) s += bfb[(l*8 + f)*128 + c];
        bbond[l*128 + c] = s;
    }
}

__global__ void k_copy_out(const float4* __restrict__ H, const float4* __restrict__ HB,
                           float4* __restrict__ O, int N32, int T32)
{
    int t = blockIdx.x*blockDim.x + threadIdx.x;
    if (t >= T32) return;
    O[t] = (t < N32) ? H[t] : HB[t - N32];
}

// ---------------- launcher ---------------------------------------------------
extern "C" void kernel_launch(void* const* d_in, const int* in_sizes, int n_in,
                              void* d_out, int out_size)
{
    const int N = NN, E = EE, A = AA;

    const int*   x_atom      = (const int*)  d_in[0];
    const int*   edge_index  = (const int*)  d_in[1];
    const int*   eint        = (const int*)  d_in[2];
    const int*   eiba        = (const int*)  d_in[3];
    const float* eaf         = (const float*)d_in[4];
    const float* eab         = (const float*)d_in[5];
    const float* atom_tables = (const float*)d_in[6];
    const float* bond_tables = (const float*)d_in[7];
    const float* bf_W        = (const float*)d_in[8];
    const float* bf_b        = (const float*)d_in[9];
    const float* ba_W_ang    = (const float*)d_in[10];
    const float* ba_b_ang    = (const float*)d_in[11];
    const float* ba_W_rest   = (const float*)d_in[12];
    const float* ba_b_rest   = (const float*)d_in[13];
    const float* eps_a       = (const float*)d_in[14];
    const float* W1_a        = (const float*)d_in[15];
    const float* b1_a        = (const float*)d_in[16];
    const float* bng_a       = (const float*)d_in[17];
    const float* bnb_a       = (const float*)d_in[18];
    const float* W2_a        = (const float*)d_in[19];
    const float* b2_a        = (const float*)d_in[20];
    const float* eps_g       = (const float*)d_in[21];
    const float* W1_g        = (const float*)d_in[22];
    const float* b1_g        = (const float*)d_in[23];
    const float* bng_g       = (const float*)d_in[24];
    const float* bnb_g       = (const float*)d_in[25];
    const float* W2_g        = (const float*)d_in[26];
    const float* b2_g        = (const float*)d_in[27];
    const float* obng_a      = (const float*)d_in[28];
    const float* obnb_a      = (const float*)d_in[29];
    const float* obng_ba     = (const float*)d_in[30];
    const float* obnb_ba     = (const float*)d_in[31];

    const int* src  = edge_index;
    const int* dst  = edge_index + E;
    const int* srcb = eiba;
    const int* dstb = eiba + A;

    float *ph, *phb, *ppre, *pt, *pembB, *pang, *pAb, *pAa;
    float *pWang, *pbang, *pbbond, *pstats, *pbns, *pbnsh, *pobs, *pobsh;
    cudaGetSymbolAddress((void**)&ph,    g_h);
    cudaGetSymbolAddress((void**)&phb,   g_hb);
    cudaGetSymbolAddress((void**)&ppre,  g_pre);
    cudaGetSymbolAddress((void**)&pt,    g_t);
    cudaGetSymbolAddress((void**)&pembB, g_embB);
    cudaGetSymbolAddress((void**)&pang,  g_ang);
    cudaGetSymbolAddress((void**)&pAb,   g_Abond);
    cudaGetSymbolAddress((void**)&pAa,   g_Aang);
    cudaGetSymbolAddress((void**)&pWang, g_Wang);
    cudaGetSymbolAddress((void**)&pbang, g_bang);
    cudaGetSymbolAddress((void**)&pbbond,g_bbond);
    cudaGetSymbolAddress((void**)&pstats,g_stats);
    cudaGetSymbolAddress((void**)&pbns,  g_bns);
    cudaGetSymbolAddress((void**)&pbnsh, g_bnsh);
    cudaGetSymbolAddress((void**)&pobs,  g_obs);
    cudaGetSymbolAddress((void**)&pobsh, g_obsh);

    auto blks = [](int n){ return (n + 255) / 256; };
    const int gN = (N+127)/128, gE = (E+127)/128, gA = (A+127)/128;

    // --- one-time (per call) precompute ---
    k_pack<<<1,128>>>(ba_W_ang, ba_W_rest, ba_b_ang, ba_b_rest, bf_b,
                      pWang, pbang, pbbond);
    k_rbf_bond<<<E, 240>>>(eaf, pAb);
    k_rbf_ang<<<(A + 7)/8, 320>>>(eab, pAa, A);

    // --- initial embeddings ---
    k_atom_embed<<<blks(N*32),256>>>(x_atom, (const float4*)atom_tables, (float4*)ph, N*32);
    k_bond_int_embed<<<blks(E*32),256>>>(eint, (const float4*)bond_tables, (float4*)phb, E*32);
    gemm_mma<false,false,true><<<gE,256>>>(pAb, KB, KB, bf_W, pbbond,
                                           phb, E, nullptr, nullptr, nullptr);

    for (int l = 0; l < LL; ++l) {
        const bool last = (l == LL - 1);

        // ===== atom GIN conv =====
        k_init_pre<<<blks(N*32),256>>>((const float4*)ph, (float4*)ppre, N*32, eps_a + l, pstats);
        k_scatter<<<blks(E*32),256>>>((const float4*)ph, (const float4*)phb, src, dst,
                                      (float4*)ppre, E*32);
        gemm_mma<false,true,false><<<gN,256>>>(ppre, 128, 128,
            W1_a + l*16384, b1_a + l*128, pt, N, nullptr, nullptr, pstats);
        k_bn_finalize<<<1,128>>>(pstats, bng_a + l*128, bnb_a + l*128, 1.0f/N, pbns, pbnsh);
        if (!last) {
            gemm_mma<true,true,false><<<gN,256>>>(pt, 128, 128,
                W2_a + l*16384, b2_a + l*128, ph, N, pbns, pbnsh, pstats);
            k_bn_finalize<<<1,128>>>(pstats, obng_a + l*128, obnb_a + l*128, 1.0f/N, pobs, pobsh);
            k_bnrelu<<<blks(N*32),256>>>((float4*)ph, N*32, pobs, pobsh);
        } else {
            gemm_mma<true,false,false><<<gN,256>>>(pt, 128, 128,
                W2_a + l*16384, b2_a + l*128, ph, N, pbns, pbnsh, nullptr);
        }

        // ===== bond embeddings for layer l+1 =====
        k_bond_int_embed<<<blks(E*32),256>>>(eint,
            (const float4*)(bond_tables + (l+1)*3*12*128), (float4*)pembB, E*32);
        gemm_mma<false,false,true><<<gE,256>>>(pAb, KB, KB,
            bf_W + (l+1)*KB*128, pbbond + (l+1)*128, pembB, E, nullptr, nullptr, nullptr);
        gemm_mma<false,false,false><<<gA,256>>>(pAa, KAP, KAP,
            pWang + l*KAP*128, pbang + l*128, pang, A, nullptr, nullptr, nullptr);

        // ===== bond GIN conv =====
        k_init_pre<<<blks(E*32),256>>>((const float4*)pembB, (float4*)ppre, E*32, eps_g + l, pstats);
        k_scatter<<<blks(A*32),256>>>((const float4*)pembB, (const float4*)pang, srcb, dstb,
                                      (float4*)ppre, A*32);
        gemm_mma<false,true,false><<<gE,256>>>(ppre, 128, 128,
            W1_g + l*16384, b1_g + l*128, pt, E, nullptr, nullptr, pstats);
        k_bn_finalize<<<1,128>>>(pstats, bng_g + l*128, bnb_g + l*128, 1.0f/E, pbns, pbnsh);
        if (!last) {
            gemm_mma<true,true,false><<<gE,256>>>(pt, 128, 128,
                W2_g + l*16384, b2_g + l*128, phb, E, pbns, pbnsh, pstats);
            k_bn_finalize<<<1,128>>>(pstats, obng_ba + l*128, obnb_ba + l*128, 1.0f/E, pobs, pobsh);
            k_bnrelu<<<blks(E*32),256>>>((float4*)phb, E*32, pobs, pobsh);
        } else {
            gemm_mma<true,false,false><<<gE,256>>>(pt, 128, 128,
                W2_g + l*16384, b2_g + l*128, phb, E, pbns, pbnsh, nullptr);
        }
    }

    // --- output: [h (N*128) ; h_ba (E*128)] ---
    int T32 = (N + E) * 32;
    k_copy_out<<<blks(T32),256>>>((const float4*)ph, (const float4*)phb,
                                  (float4*)d_out, N*32, T32);
}

// round 5
// speedup vs baseline: 1.3708x; 1.2042x over previous
#include <cuda_runtime.h>
#include <cuda_bf16.h>
#include <math.h>

#define NN 100000
#define EE 200000
#define AA 400000
#define LL 5

// ---------------- scratch (static device globals; no runtime alloc) ----------
__device__ float g_h[NN*128];
__device__ float g_hb[EE*128];
__device__ float g_pre[EE*128];
__device__ float g_t[EE*128];
__device__ float g_embB[EE*128];
__device__ float g_ang[AA*128];

// pre-split pair-packed bf16 operands (each uint = bf16(k) | bf16(k+1)<<16)
__device__ unsigned g_Aph[EE*64],  g_Apl[EE*64];    // activation splits (ldp=64)
__device__ unsigned g_Abh[EE*128], g_Abl[EE*128];   // bond RBF basis (K=256 -> ldp=128)
__device__ unsigned g_Aah[AA*32],  g_Aal[AA*32];    // angle basis (K=64 -> ldp=32)
// weights, [batch][kp][n] pair-packed
__device__ unsigned g_W1ah[LL*64*128], g_W1al[LL*64*128];
__device__ unsigned g_W2ah[LL*64*128], g_W2al[LL*64*128];
__device__ unsigned g_W1gh[LL*64*128], g_W1gl[LL*64*128];
__device__ unsigned g_W2gh[LL*64*128], g_W2gl[LL*64*128];
__device__ unsigned g_bfWh[(LL+1)*128*128], g_bfWl[(LL+1)*128*128];
__device__ unsigned g_Wgah[LL*32*128],  g_Wgal[LL*32*128];

__device__ float g_Wang[LL*64*128];   // packed angle weight (fp32 K-major, padded 64)
__device__ float g_bang[LL*128];
__device__ float g_bbond[(LL+1)*128];
__device__ float g_stats[256];
__device__ float g_bns[128];
__device__ float g_bnsh[128];
__device__ float g_obs[128];
__device__ float g_obsh[128];

__constant__ double c_bf_start[8] = {0.0,0.0,3.0,0.0,0.0,0.0,0.0,0.0};
__constant__ double c_bf_step[8]  = {0.1,0.05,0.3,0.05,0.05,0.05,0.5,0.05};
__constant__ int    c_bf_cnt[8]   = {20,20,30,20,20,20,20,20};
__constant__ float  c_bf_g[8]     = {10.f,1.f,1.f,1.f,1.f,1.f,2.f,1.f};

// ---------------- helpers -----------------------------------------------------
__device__ __forceinline__ void split_pack(float x, float y, unsigned &hi, unsigned &lo)
{
    __nv_bfloat16 bx = __float2bfloat16_rn(x);
    __nv_bfloat16 by = __float2bfloat16_rn(y);
    float rx = x - __bfloat162float(bx);
    float ry = y - __bfloat162float(by);
    __nv_bfloat16 brx = __float2bfloat16_rn(rx);
    __nv_bfloat16 bry = __float2bfloat16_rn(ry);
    hi = ((unsigned)__bfloat16_as_ushort(by) << 16) | __bfloat16_as_ushort(bx);
    lo = ((unsigned)__bfloat16_as_ushort(bry) << 16) | __bfloat16_as_ushort(brx);
}

#define MMA_BF16(d, a0,a1,a2,a3, b0,b1) \
    asm volatile( \
        "mma.sync.aligned.m16n8k16.row.col.f32.bf16.bf16.f32 " \
        "{%0,%1,%2,%3}, {%4,%5,%6,%7}, {%8,%9}, {%0,%1,%2,%3};" \
        : "+f"(d[0]), "+f"(d[1]), "+f"(d[2]), "+f"(d[3]) \
        : "r"(a0), "r"(a1), "r"(a2), "r"(a3), "r"(b0), "r"(b1))

// ---------------- persistent bf16x3 mma GEMM ---------------------------------
// Y[M,128] = A[M, 2*ldp] @ W^T + bias  (A,W pre-split pair-packed bf16 hi/lo)
// W resident in smem for all tiles of this CTA. STATS: col sum/sumsq (fused,
// register-accumulated across tiles, flushed once). ACCUM: Y += result.
template<bool STATS, bool ACCUM>
__global__ void __launch_bounds__(256,1) gemm_ps(
    const unsigned* __restrict__ Aph, const unsigned* __restrict__ Apl, int ldp,
    const unsigned* __restrict__ Wph, const unsigned* __restrict__ Wpl,
    const float* __restrict__ bias, float* __restrict__ Y, int M,
    float* __restrict__ stats)
{
    extern __shared__ unsigned dyn[];
    const int chunks = ldp >> 4;        // 16 pairs (32 k) per chunk
    unsigned* Wsh = dyn;
    unsigned* Wsl = dyn + chunks*2048;
    unsigned* Ash = dyn + 2*chunks*2048;
    unsigned* Asl = Ash + 2048;
    __shared__ float sSum[128], sSq[128];

    const int tid  = threadIdx.x;
    const int lane = tid & 31;
    const int warp = tid >> 5;
    const int wm = warp >> 2;   // 0..1
    const int wn = warp & 3;    // 0..3

    if (STATS && tid < 128) { sSum[tid] = 0.f; sSq[tid] = 0.f; }

    // ---- stage W once (fragment-native, pair-packed) ----
    for (int i = tid; i < chunks*512; i += 256) {
        int c    = i >> 9;
        int j    = i & 511;
        int kpl  = j >> 5;              // local pair row 0..15
        int col0 = (j & 31) << 2;       // col quad base
        int kp   = c*16 + kpl;
        uint4 vh = *(const uint4*)(Wph + kp*128 + col0);
        uint4 vl = *(const uint4*)(Wpl + kp*128 + col0);
        int s = kpl >> 3, pp = kpl & 7, tig = pp & 3, reg = pp >> 2;
        int nt = col0 >> 3;
        int b0 = ((((nt<<1)+s)<<5) + ((col0 & 7)<<2) + tig);
        unsigned* wh = Wsh + c*2048;
        unsigned* wl = Wsl + c*2048;
        wh[(b0+0)*2+reg] = vh.x; wh[(b0+4)*2+reg] = vh.y;
        wh[(b0+8)*2+reg] = vh.z; wh[(b0+12)*2+reg] = vh.w;
        wl[(b0+0)*2+reg] = vl.x; wl[(b0+4)*2+reg] = vl.y;
        wl[(b0+8)*2+reg] = vl.z; wl[(b0+12)*2+reg] = vl.w;
    }

    // hoisted bias and stats registers (cols are tile-invariant)
    const int colq = (lane & 3) << 1;
    float bv[4][2];
#pragma unroll
    for (int ni = 0; ni < 4; ++ni) {
        int c = wn*32 + ni*8 + colq;
        bv[ni][0] = bias[c];
        bv[ni][1] = bias[c+1];
    }
    float cs[4][2], cq[4][2];
#pragma unroll
    for (int ni=0;ni<4;++ni){ cs[ni][0]=cs[ni][1]=0.f; cq[ni][0]=cq[ni][1]=0.f; }

    const int ntiles = (M + 127) >> 7;
    for (int tile = blockIdx.x; tile < ntiles; tile += gridDim.x) {
        const int m0 = tile << 7;

        float acc[4][4][4];
#pragma unroll
        for (int i=0;i<4;++i)
#pragma unroll
            for (int j=0;j<4;++j)
#pragma unroll
                for (int r=0;r<4;++r) acc[i][j][r] = 0.f;

        for (int ch = 0; ch < chunks; ++ch) {
            __syncthreads();   // protect Ash from previous compute / init visibility
            // ---- stage A chunk ----
#pragma unroll
            for (int it = 0; it < 2; ++it) {
                int i2  = tid + it*256;
                int row = i2 >> 2, q = i2 & 3;
                uint4 vh = make_uint4(0,0,0,0), vl = make_uint4(0,0,0,0);
                int grow = m0 + row;
                if (grow < M) {
                    long off = (long)grow*ldp + ch*16 + (q << 2);
                    vh = *(const uint4*)(Aph + off);
                    vl = *(const uint4*)(Apl + off);
                }
                int s  = q >> 1, ph = q & 1;
                int reg = ((row >> 3) & 1) | (ph << 1);
                int b0 = ((((row >> 4) << 1) + s) << 5) + ((row & 7) << 2);
                Ash[(b0+0)*4+reg] = vh.x; Ash[(b0+1)*4+reg] = vh.y;
                Ash[(b0+2)*4+reg] = vh.z; Ash[(b0+3)*4+reg] = vh.w;
                Asl[(b0+0)*4+reg] = vl.x; Asl[(b0+1)*4+reg] = vl.y;
                Asl[(b0+2)*4+reg] = vl.z; Asl[(b0+3)*4+reg] = vl.w;
            }
            __syncthreads();

            // ---- compute: 2 k16 steps, 4x4 warp tiles, bf16x3 ----
            const unsigned* wh = Wsh + ch*2048;
            const unsigned* wl = Wsl + ch*2048;
#pragma unroll
            for (int s = 0; s < 2; ++s) {
                unsigned bh[4][2], bl[4][2];
#pragma unroll
                for (int ni = 0; ni < 4; ++ni) {
                    int base = (((((wn*4 + ni) << 1) + s) << 5) | lane) << 1;
                    uint2 fh = *(const uint2*)&wh[base];
                    uint2 fl = *(const uint2*)&wl[base];
                    bh[ni][0]=fh.x; bh[ni][1]=fh.y;
                    bl[ni][0]=fl.x; bl[ni][1]=fl.y;
                }
#pragma unroll
                for (int mi = 0; mi < 4; ++mi) {
                    int base = (((((wm*4 + mi) << 1) + s) << 5) | lane) << 2;
                    uint4 ah = *(const uint4*)&Ash[base];
                    uint4 al = *(const uint4*)&Asl[base];
#pragma unroll
                    for (int ni = 0; ni < 4; ++ni) {
                        MMA_BF16(acc[mi][ni], ah.x, ah.y, ah.z, ah.w, bh[ni][0], bh[ni][1]);
                        MMA_BF16(acc[mi][ni], ah.x, ah.y, ah.z, ah.w, bl[ni][0], bl[ni][1]);
                        MMA_BF16(acc[mi][ni], al.x, al.y, al.z, al.w, bh[ni][0], bh[ni][1]);
                    }
                }
            }
        }

        // ---- epilogue ----
#pragma unroll
        for (int mi = 0; mi < 4; ++mi) {
#pragma unroll
            for (int half = 0; half < 2; ++half) {
                int row = m0 + wm*64 + mi*16 + (lane >> 2) + half*8;
                if (row < M) {
#pragma unroll
                    for (int ni = 0; ni < 4; ++ni) {
                        int c = wn*32 + ni*8 + colq;
                        float y0 = acc[mi][ni][half*2+0] + bv[ni][0];
                        float y1 = acc[mi][ni][half*2+1] + bv[ni][1];
                        float* yp = Y + (long)row*128 + c;
                        if (ACCUM) { y0 += yp[0]; y1 += yp[1]; }
                        *(float2*)yp = make_float2(y0, y1);
                        if (STATS) {
                            cs[ni][0] += y0; cs[ni][1] += y1;
                            cq[ni][0] += y0*y0; cq[ni][1] += y1*y1;
                        }
                    }
                }
            }
        }
    }

    if (STATS) {
        __syncthreads();
#pragma unroll
        for (int ni = 0; ni < 4; ++ni) {
            int c = wn*32 + ni*8 + colq;
            atomicAdd(&sSum[c],   cs[ni][0]);
            atomicAdd(&sSum[c+1], cs[ni][1]);
            atomicAdd(&sSq[c],    cq[ni][0]);
            atomicAdd(&sSq[c+1],  cq[ni][1]);
        }
        __syncthreads();
        if (tid < 128) {
            atomicAdd(&stats[tid],     sSum[tid]);
            atomicAdd(&stats[128+tid], sSq[tid]);
        }
    }
}

// ---------------- split fp32 -> pair-packed bf16 hi/lo (optional bn-relu) ----
template<bool TR>
__global__ void k_split(const float4* __restrict__ X, uint2* __restrict__ Xh,
                        uint2* __restrict__ Xl, int M32,
                        const float* __restrict__ sc, const float* __restrict__ sh)
{
    int t = blockIdx.x*blockDim.x + threadIdx.x;
    if (t >= M32) return;
    float4 v = X[t];
    if (TR) {
        int cb = (t & 31) << 2;
        v.x = fmaxf(fmaf(v.x, sc[cb+0], sh[cb+0]), 0.f);
        v.y = fmaxf(fmaf(v.y, sc[cb+1], sh[cb+1]), 0.f);
        v.z = fmaxf(fmaf(v.z, sc[cb+2], sh[cb+2]), 0.f);
        v.w = fmaxf(fmaf(v.w, sc[cb+3], sh[cb+3]), 0.f);
    }
    unsigned h01, l01, h23, l23;
    split_pack(v.x, v.y, h01, l01);
    split_pack(v.z, v.w, h23, l23);
    Xh[t] = make_uint2(h01, h23);
    Xl[t] = make_uint2(l01, l23);
}

// weight transpose+split: W[b][K][128] fp32 -> [b][kp][n] pair-packed
__global__ void k_splitW(const float* __restrict__ W, unsigned* __restrict__ dh,
                         unsigned* __restrict__ dl, int K, int Kp2, int total)
{
    int idx = blockIdx.x*blockDim.x + threadIdx.x;
    if (idx >= total) return;
    int b   = idx / (Kp2*128);
    int rem = idx - b*Kp2*128;
    int kp  = rem >> 7;
    int n   = rem & 127;
    int k0 = kp*2, k1 = k0 + 1;
    float v0 = (k0 < K) ? W[(long)b*K*128 + (long)k0*128 + n] : 0.f;
    float v1 = (k1 < K) ? W[(long)b*K*128 + (long)k1*128 + n] : 0.f;
    unsigned h, l;
    split_pack(v0, v1, h, l);
    dh[idx] = h; dl[idx] = l;
}

// ---------------- GIN helpers -----------------------------------------------
__global__ void k_init_pre(const float4* __restrict__ X, float4* __restrict__ P,
                           int M32, const float* __restrict__ epsP)
{
    int t = blockIdx.x*blockDim.x + threadIdx.x;
    if (t >= M32) return;
    float e = 1.f + *epsP;
    float4 x = X[t];
    x.x *= e; x.y *= e; x.z *= e; x.w *= e;
    P[t] = x;
}

__global__ void k_scatter(const float4* __restrict__ X, const float4* __restrict__ EA,
                          const int* __restrict__ src, const int* __restrict__ dst,
                          float4* __restrict__ P, int E32)
{
    int t = blockIdx.x*blockDim.x + threadIdx.x;
    if (t >= E32) return;
    int e = t >> 5, l = t & 31;
    int s = src[e], d = dst[e];
    float4 x = X[s*32 + l];
    float4 a = EA[(e<<5) + l];
    float4 m;
    m.x = fmaxf(x.x + a.x, 0.f);
    m.y = fmaxf(x.y + a.y, 0.f);
    m.z = fmaxf(x.z + a.z, 0.f);
    m.w = fmaxf(x.w + a.w, 0.f);
#if defined(__CUDA_ARCH__) && (__CUDA_ARCH__ >= 900)
    atomicAdd(&P[d*32 + l], m);
#else
    float* p = (float*)&P[d*32 + l];
    atomicAdd(p+0, m.x); atomicAdd(p+1, m.y);
    atomicAdd(p+2, m.z); atomicAdd(p+3, m.w);
#endif
}

__global__ void k_bn_finalize(float* __restrict__ stats, const float* __restrict__ g,
                              const float* __restrict__ b, float invM,
                              float* __restrict__ oscale, float* __restrict__ oshift)
{
    int c = threadIdx.x;   // 128
    float mu  = stats[c] * invM;
    float var = stats[128+c] * invM - mu*mu;
    float rs  = rsqrtf(var + 1e-5f);
    float scv = g[c] * rs;
    oscale[c] = scv;
    oshift[c] = b[c] - mu*scv;
    stats[c] = 0.f;
    stats[128+c] = 0.f;
}

__global__ void k_bnrelu(float4* __restrict__ X, int M32,
                         const float* __restrict__ sc, const float* __restrict__ sh)
{
    int t = blockIdx.x*blockDim.x + threadIdx.x;
    if (t >= M32) return;
    int cb = (t & 31) << 2;
    float4 v = X[t];
    v.x = fmaxf(fmaf(v.x, sc[cb+0], sh[cb+0]), 0.f);
    v.y = fmaxf(fmaf(v.y, sc[cb+1], sh[cb+1]), 0.f);
    v.z = fmaxf(fmaf(v.z, sc[cb+2], sh[cb+2]), 0.f);
    v.w = fmaxf(fmaf(v.w, sc[cb+3], sh[cb+3]), 0.f);
    X[t] = v;
}

// ---------------- embeddings ------------------------------------------------
__global__ void k_atom_embed(const int* __restrict__ xa, const float4* __restrict__ tab,
                             float4* __restrict__ H, int N32)
{
    int t = blockIdx.x*blockDim.x + threadIdx.x;
    if (t >= N32) return;
    int n = t >> 5, l = t & 31;
    float4 s = make_float4(0.f,0.f,0.f,0.f);
#pragma unroll
    for (int f=0; f<9; ++f) {
        int idx = xa[n*9 + f];
        float4 v = tab[(f*124 + idx)*32 + l];
        s.x += v.x; s.y += v.y; s.z += v.z; s.w += v.w;
    }
    H[t] = s;
}

__global__ void k_bond_int_embed(const int* __restrict__ ei, const float4* __restrict__ tab,
                                 float4* __restrict__ O, int E32)
{
    int t = blockIdx.x*blockDim.x + threadIdx.x;
    if (t >= E32) return;
    int e = t >> 5, l = t & 31;
    float4 s = make_float4(0.f,0.f,0.f,0.f);
#pragma unroll
    for (int f=0; f<3; ++f) {
        int idx = ei[e*3 + f];
        float4 v = tab[(f*12 + idx)*32 + l];
        s.x += v.x; s.y += v.y; s.z += v.z; s.w += v.w;
    }
    O[t] = s;
}

__device__ __forceinline__ float bond_rbf_val(const float* xf, int e, int k)
{
    if (k >= 240) return 0.f;
    int f = k / 30, c = k % 30;
    if (c >= c_bf_cnt[f]) return 0.f;
    float x = xf[e*8 + f];
    float ctr = (float)(c_bf_start[f] + c_bf_step[f] * (double)c);
    float d = x - ctr;
    return expf(-c_bf_g[f] * d * d);
}

__global__ void k_rbf_bond(const float* __restrict__ xf,
                           unsigned* __restrict__ Ah, unsigned* __restrict__ Al)
{
    int e = blockIdx.x;
    int kp = threadIdx.x;   // 0..127 pairs (K=256)
    float v0 = bond_rbf_val(xf, e, 2*kp);
    float v1 = bond_rbf_val(xf, e, 2*kp + 1);
    unsigned h, l;
    split_pack(v0, v1, h, l);
    Ah[e*128 + kp] = h; Al[e*128 + kp] = l;
}

__device__ __forceinline__ float ang_val(const float* xa, int a, int k)
{
    if (k < 32) {
        float ctr = (float)((double)k * 0.1);
        float d = xa[a*6] - ctr;
        return expf(-10.f * d * d);
    } else if (k < 37) {
        return xa[a*6 + (k - 31)];
    }
    return 0.f;
}

__global__ void k_rbf_ang(const float* __restrict__ xa,
                          unsigned* __restrict__ Ah, unsigned* __restrict__ Al, int A)
{
    int idx = blockIdx.x*blockDim.x + threadIdx.x;
    int a = idx >> 5, kp = idx & 31;   // 32 pairs (K=64)
    if (a >= A) return;
    float v0 = ang_val(xa, a, 2*kp);
    float v1 = ang_val(xa, a, 2*kp + 1);
    unsigned h, l;
    split_pack(v0, v1, h, l);
    Ah[a*32 + kp] = h; Al[a*32 + kp] = l;
}

// pack angle weights [64,128] per layer (zero padded) and combined biases
__global__ void k_pack(const float* __restrict__ baWang, const float* __restrict__ baWrest,
                       const float* __restrict__ baBang, const float* __restrict__ baBrest,
                       const float* __restrict__ bfb,
                       float* __restrict__ Wang, float* __restrict__ bang,
                       float* __restrict__ bbond)
{
    int c = threadIdx.x;   // 128
    for (int l=0; l<LL; ++l) {
        for (int r=0; r<64; ++r) {
            float v = 0.f;
            if (r < 32)      v = baWang[(l*32 + r)*128 + c];
            else if (r < 37) v = baWrest[(l*5 + (r-32))*128 + c];
            Wang[(l*64 + r)*128 + c] = v;
        }
        bang[l*128 + c] = baBang[l*128 + c] + baBrest[l*128 + c];
    }
    for (int l=0; l<=LL; ++l) {
        float s = 0.f;
        for (int f=0; f<8; ++f) s += bfb[(l*8 + f)*128 + c];
        bbond[l*128 + c] = s;
    }
}

__global__ void k_copy_out(const float4* __restrict__ H, const float4* __restrict__ HB,
                           float4* __restrict__ O, int N32, int T32)
{
    int t = blockIdx.x*blockDim.x + threadIdx.x;
    if (t >= T32) return;
    O[t] = (t < N32) ? H[t] : HB[t - N32];
}

// ---------------- launcher ---------------------------------------------------
extern "C" void kernel_launch(void* const* d_in, const int* in_sizes, int n_in,
                              void* d_out, int out_size)
{
    const int N = NN, E = EE, A = AA;

    const int*   x_atom      = (const int*)  d_in[0];
    const int*   edge_index  = (const int*)  d_in[1];
    const int*   eint        = (const int*)  d_in[2];
    const int*   eiba        = (const int*)  d_in[3];
    const float* eaf         = (const float*)d_in[4];
    const float* eab         = (const float*)d_in[5];
    const float* atom_tables = (const float*)d_in[6];
    const float* bond_tables = (const float*)d_in[7];
    const float* bf_W        = (const float*)d_in[8];
    const float* bf_b        = (const float*)d_in[9];
    const float* ba_W_ang    = (const float*)d_in[10];
    const float* ba_b_ang    = (const float*)d_in[11];
    const float* ba_W_rest   = (const float*)d_in[12];
    const float* ba_b_rest   = (const float*)d_in[13];
    const float* eps_a       = (const float*)d_in[14];
    const float* W1_a        = (const float*)d_in[15];
    const float* b1_a        = (const float*)d_in[16];
    const float* bng_a       = (const float*)d_in[17];
    const float* bnb_a       = (const float*)d_in[18];
    const float* W2_a        = (const float*)d_in[19];
    const float* b2_a        = (const float*)d_in[20];
    const float* eps_g       = (const float*)d_in[21];
    const float* W1_g        = (const float*)d_in[22];
    const float* b1_g        = (const float*)d_in[23];
    const float* bng_g       = (const float*)d_in[24];
    const float* bnb_g       = (const float*)d_in[25];
    const float* W2_g        = (const float*)d_in[26];
    const float* b2_g        = (const float*)d_in[27];
    const float* obng_a      = (const float*)d_in[28];
    const float* obnb_a      = (const float*)d_in[29];
    const float* obng_ba     = (const float*)d_in[30];
    const float* obnb_ba     = (const float*)d_in[31];

    const int* src  = edge_index;
    const int* dst  = edge_index + E;
    const int* srcb = eiba;
    const int* dstb = eiba + A;

    float *ph, *phb, *ppre, *pt, *pembB, *pang;
    float *pWang, *pbang, *pbbond, *pstats, *pbns, *pbnsh, *pobs, *pobsh;
    unsigned *Aph,*Apl,*Abh,*Abl,*Aah,*Aal;
    unsigned *W1ah,*W1al,*W2ah,*W2al,*W1gh,*W1gl,*W2gh,*W2gl,*bfWh,*bfWl,*Wgah,*Wgal;
    cudaGetSymbolAddress((void**)&ph,    g_h);
    cudaGetSymbolAddress((void**)&phb,   g_hb);
    cudaGetSymbolAddress((void**)&ppre,  g_pre);
    cudaGetSymbolAddress((void**)&pt,    g_t);
    cudaGetSymbolAddress((void**)&pembB, g_embB);
    cudaGetSymbolAddress((void**)&pang,  g_ang);
    cudaGetSymbolAddress((void**)&pWang, g_Wang);
    cudaGetSymbolAddress((void**)&pbang, g_bang);
    cudaGetSymbolAddress((void**)&pbbond,g_bbond);
    cudaGetSymbolAddress((void**)&pstats,g_stats);
    cudaGetSymbolAddress((void**)&pbns,  g_bns);
    cudaGetSymbolAddress((void**)&pbnsh, g_bnsh);
    cudaGetSymbolAddress((void**)&pobs,  g_obs);
    cudaGetSymbolAddress((void**)&pobsh, g_obsh);
    cudaGetSymbolAddress((void**)&Aph,   g_Aph);
    cudaGetSymbolAddress((void**)&Apl,   g_Apl);
    cudaGetSymbolAddress((void**)&Abh,   g_Abh);
    cudaGetSymbolAddress((void**)&Abl,   g_Abl);
    cudaGetSymbolAddress((void**)&Aah,   g_Aah);
    cudaGetSymbolAddress((void**)&Aal,   g_Aal);
    cudaGetSymbolAddress((void**)&W1ah,  g_W1ah); cudaGetSymbolAddress((void**)&W1al, g_W1al);
    cudaGetSymbolAddress((void**)&W2ah,  g_W2ah); cudaGetSymbolAddress((void**)&W2al, g_W2al);
    cudaGetSymbolAddress((void**)&W1gh,  g_W1gh); cudaGetSymbolAddress((void**)&W1gl, g_W1gl);
    cudaGetSymbolAddress((void**)&W2gh,  g_W2gh); cudaGetSymbolAddress((void**)&W2gl, g_W2gl);
    cudaGetSymbolAddress((void**)&bfWh,  g_bfWh); cudaGetSymbolAddress((void**)&bfWl, g_bfWl);
    cudaGetSymbolAddress((void**)&Wgah,  g_Wgah); cudaGetSymbolAddress((void**)&Wgal, g_Wgal);

    // dynamic smem opt-in for the largest case (chunks=8 -> 147456 B)
    cudaFuncSetAttribute(gemm_ps<false,false>, cudaFuncAttributeMaxDynamicSharedMemorySize, 147456);
    cudaFuncSetAttribute(gemm_ps<true,false>,  cudaFuncAttributeMaxDynamicSharedMemorySize, 147456);
    cudaFuncSetAttribute(gemm_ps<false,true>,  cudaFuncAttributeMaxDynamicSharedMemorySize, 147456);

    auto blks = [](int n){ return (n + 255) / 256; };
    auto dynB = [](int chunks){ return (2*chunks + 2) * 2048 * 4; };
    auto gsz  = [](int M){ int t = (M+127)/128; return t < 148 ? t : 148; };

    // --- one-time (per call) precompute ---
    k_pack<<<1,128>>>(ba_W_ang, ba_W_rest, ba_b_ang, ba_b_rest, bf_b,
                      pWang, pbang, pbbond);
    k_splitW<<<blks(LL*64*128),256>>>(W1_a, W1ah, W1al, 128, 64, LL*64*128);
    k_splitW<<<blks(LL*64*128),256>>>(W2_a, W2ah, W2al, 128, 64, LL*64*128);
    k_splitW<<<blks(LL*64*128),256>>>(W1_g, W1gh, W1gl, 128, 64, LL*64*128);
    k_splitW<<<blks(LL*64*128),256>>>(W2_g, W2gh, W2gl, 128, 64, LL*64*128);
    k_splitW<<<blks((LL+1)*128*128),256>>>(bf_W, bfWh, bfWl, 240, 128, (LL+1)*128*128);
    k_splitW<<<blks(LL*32*128),256>>>(pWang, Wgah, Wgal, 64, 32, LL*32*128);
    k_rbf_bond<<<E, 128>>>(eaf, Abh, Abl);
    k_rbf_ang<<<blks(A*32),256>>>(eab, Aah, Aal, A);

    // --- initial embeddings ---
    k_atom_embed<<<blks(N*32),256>>>(x_atom, (const float4*)atom_tables, (float4*)ph, N*32);
    k_bond_int_embed<<<blks(E*32),256>>>(eint, (const float4*)bond_tables, (float4*)phb, E*32);
    gemm_ps<false,true><<<gsz(E),256,dynB(8)>>>(Abh, Abl, 128, bfWh, bfWl,
                                                pbbond, phb, E, nullptr);

    for (int l = 0; l < LL; ++l) {
        const bool last = (l == LL - 1);

        // ===== atom GIN conv =====
        k_init_pre<<<blks(N*32),256>>>((const float4*)ph, (float4*)ppre, N*32, eps_a + l);
        k_scatter<<<blks(E*32),256>>>((const float4*)ph, (const float4*)phb, src, dst,
                                      (float4*)ppre, E*32);
        k_split<false><<<blks(N*32),256>>>((const float4*)ppre, (uint2*)Aph, (uint2*)Apl,
                                           N*32, nullptr, nullptr);
        gemm_ps<true,false><<<gsz(N),256,dynB(4)>>>(Aph, Apl, 64,
            W1ah + l*8192, W1al + l*8192, b1_a + l*128, pt, N, pstats);
        k_bn_finalize<<<1,128>>>(pstats, bng_a + l*128, bnb_a + l*128, 1.0f/N, pbns, pbnsh);
        k_split<true><<<blks(N*32),256>>>((const float4*)pt, (uint2*)Aph, (uint2*)Apl,
                                          N*32, pbns, pbnsh);
        if (!last) {
            gemm_ps<true,false><<<gsz(N),256,dynB(4)>>>(Aph, Apl, 64,
                W2ah + l*8192, W2al + l*8192, b2_a + l*128, ph, N, pstats);
            k_bn_finalize<<<1,128>>>(pstats, obng_a + l*128, obnb_a + l*128, 1.0f/N, pobs, pobsh);
            k_bnrelu<<<blks(N*32),256>>>((float4*)ph, N*32, pobs, pobsh);
        } else {
            gemm_ps<false,false><<<gsz(N),256,dynB(4)>>>(Aph, Apl, 64,
                W2ah + l*8192, W2al + l*8192, b2_a + l*128, ph, N, nullptr);
        }

        // ===== bond embeddings for layer l+1 =====
        k_bond_int_embed<<<blks(E*32),256>>>(eint,
            (const float4*)(bond_tables + (l+1)*3*12*128), (float4*)pembB, E*32);
        gemm_ps<false,true><<<gsz(E),256,dynB(8)>>>(Abh, Abl, 128,
            bfWh + (l+1)*16384, bfWl + (l+1)*16384, pbbond + (l+1)*128, pembB, E, nullptr);
        gemm_ps<false,false><<<gsz(A),256,dynB(2)>>>(Aah, Aal, 32,
            Wgah + l*4096, Wgal + l*4096, pbang + l*128, pang, A, nullptr);

        // ===== bond GIN conv =====
        k_init_pre<<<blks(E*32),256>>>((const float4*)pembB, (float4*)ppre, E*32, eps_g + l);
        k_scatter<<<blks(A*32),256>>>((const float4*)pembB, (const float4*)pang, srcb, dstb,
                                      (float4*)ppre, A*32);
        k_split<false><<<blks(E*32),256>>>((const float4*)ppre, (uint2*)Aph, (uint2*)Apl,
                                           E*32, nullptr, nullptr);
        gemm_ps<true,false><<<gsz(E),256,dynB(4)>>>(Aph, Apl, 64,
            W1gh + l*8192, W1gl + l*8192, b1_g + l*128, pt, E, pstats);
        k_bn_finalize<<<1,128>>>(pstats, bng_g + l*128, bnb_g + l*128, 1.0f/E, pbns, pbnsh);
        k_split<true><<<blks(E*32),256>>>((const float4*)pt, (uint2*)Aph, (uint2*)Apl,
                                          E*32, pbns, pbnsh);
        if (!last) {
            gemm_ps<true,false><<<gsz(E),256,dynB(4)>>>(Aph, Apl, 64,
                W2gh + l*8192, W2gl + l*8192, b2_g + l*128, phb, E, pstats);
            k_bn_finalize<<<1,128>>>(pstats, obng_ba + l*128, obnb_ba + l*128, 1.0f/E, pobs, pobsh);
            k_bnrelu<<<blks(E*32),256>>>((float4*)phb, E*32, pobs, pobsh);
        } else {
            gemm_ps<false,false><<<gsz(E),256,dynB(4)>>>(Aph, Apl, 64,
                W2gh + l*8192, W2gl + l*8192, b2_g + l*128, phb, E, nullptr);
        }
    }

    // --- output: [h (N*128) ; h_ba (E*128)] ---
    int T32 = (N + E) * 32;
    k_copy_out<<<blks(T32),256>>>((const float4*)ph, (const float4*)phb,
                                  (float4*)d_out, N*32, T32);
}

// round 6
// speedup vs baseline: 1.4009x; 1.0219x over previous
#include <cuda_runtime.h>
#include <cuda_bf16.h>
#include <math.h>

#define NN 100000
#define EE 200000
#define AA 400000
#define LL 5

// ---------------- scratch (static device globals; no runtime alloc) ----------
__device__ float g_h[NN*128];
__device__ float g_hb[EE*128];
__device__ float g_pre[EE*128];
__device__ float g_t[EE*128];
__device__ float g_embB[EE*128];

// pre-split pair-packed bf16 operands (each uint = bf16(k) | bf16(k+1)<<16)
__device__ unsigned g_Abh[EE*128], g_Abl[EE*128];   // bond RBF basis (K=256 -> 128 pairs)
__device__ unsigned g_Aah[AA*32],  g_Aal[AA*32];    // angle basis (K=64 -> 32 pairs)
// weights, [batch][kp][n] pair-packed
__device__ unsigned g_W1ah[LL*64*128], g_W1al[LL*64*128];
__device__ unsigned g_W2ah[LL*64*128], g_W2al[LL*64*128];
__device__ unsigned g_W1gh[LL*64*128], g_W1gl[LL*64*128];
__device__ unsigned g_W2gh[LL*64*128], g_W2gl[LL*64*128];
__device__ unsigned g_bfWh[(LL+1)*128*128], g_bfWl[(LL+1)*128*128];
__device__ unsigned g_Wgah[LL*32*128],  g_Wgal[LL*32*128];

__device__ float g_Wang[LL*64*128];   // packed angle weight (fp32 K-major, padded 64)
__device__ float g_bang[LL*128];
__device__ float g_bbond[(LL+1)*128];
__device__ float g_stats[256];
__device__ float g_bns[128];
__device__ float g_bnsh[128];
__device__ float g_obsAs[128], g_obsAh[128];   // persisted atom outer-BN transform
__device__ float g_obsBs[128], g_obsBh[128];   // persisted bond outer-BN transform

__constant__ double c_bf_start[8] = {0.0,0.0,3.0,0.0,0.0,0.0,0.0,0.0};
__constant__ double c_bf_step[8]  = {0.1,0.05,0.3,0.05,0.05,0.05,0.5,0.05};
__constant__ int    c_bf_cnt[8]   = {20,20,30,20,20,20,20,20};
__constant__ float  c_bf_g[8]     = {10.f,1.f,1.f,1.f,1.f,1.f,2.f,1.f};

// ---------------- helpers -----------------------------------------------------
__device__ __forceinline__ void split_pack(float x, float y, unsigned &hi, unsigned &lo)
{
    __nv_bfloat16 bx = __float2bfloat16_rn(x);
    __nv_bfloat16 by = __float2bfloat16_rn(y);
    float rx = x - __bfloat162float(bx);
    float ry = y - __bfloat162float(by);
    __nv_bfloat16 brx = __float2bfloat16_rn(rx);
    __nv_bfloat16 bry = __float2bfloat16_rn(ry);
    hi = ((unsigned)__bfloat16_as_ushort(by) << 16) | __bfloat16_as_ushort(bx);
    lo = ((unsigned)__bfloat16_as_ushort(bry) << 16) | __bfloat16_as_ushort(brx);
}

#define MMA_BF16(d, a0,a1,a2,a3, b0,b1) \
    asm volatile( \
        "mma.sync.aligned.m16n8k16.row.col.f32.bf16.bf16.f32 " \
        "{%0,%1,%2,%3}, {%4,%5,%6,%7}, {%8,%9}, {%0,%1,%2,%3};" \
        : "+f"(d[0]), "+f"(d[1]), "+f"(d[2]), "+f"(d[3]) \
        : "r"(a0), "r"(a1), "r"(a2), "r"(a3), "r"(b0), "r"(b1))

// ---------------- persistent bf16x3 mma GEMM ---------------------------------
// Y[M,128] = A[M,K] @ W^T + bias
//  FP32A: A is fp32 (split to bf16 hi/lo in staging); else pre-split pair-packed.
//  TRANSFORM (FP32A only): relu(bn()) applied to A on load via sc/sh.
//  STATS: fused col sum/sumsq, register-accumulated across tiles, flushed once.
//  EPI: 0 = plain store; 1 = store + bond-int-embed gather add;
//       2 = scatter (msg = relu(Xsrc[src]+y), atomicAdd to Pdst[dst]) — no store.
template<bool FP32A, bool TRANSFORM, bool STATS, int EPI>
__global__ void __launch_bounds__(256,1) gemm_ps(
    const void* __restrict__ Aop, const unsigned* __restrict__ Apl, int ld, int chunks,
    const unsigned* __restrict__ Wph, const unsigned* __restrict__ Wpl,
    const float* __restrict__ bias, float* __restrict__ Y, int M,
    float* __restrict__ stats, const float* __restrict__ sc, const float* __restrict__ sh,
    const int* __restrict__ srcg, const int* __restrict__ dstg,
    const float* __restrict__ Xsrc, float* __restrict__ Pdst,
    const int* __restrict__ eint, const float* __restrict__ etab)
{
    extern __shared__ unsigned dyn[];
    unsigned* Wsh = dyn;
    unsigned* Wsl = dyn + chunks*2048;
    unsigned* Ash = dyn + 2*chunks*2048;
    unsigned* Asl = Ash + 2048;
    __shared__ float sSum[128], sSq[128];

    const int tid  = threadIdx.x;
    const int lane = tid & 31;
    const int warp = tid >> 5;
    const int wm = warp >> 2;   // 0..1
    const int wn = warp & 3;    // 0..3

    if (STATS && tid < 128) { sSum[tid] = 0.f; sSq[tid] = 0.f; }

    // ---- stage W once (fragment-native, pair-packed) ----
    for (int i = tid; i < chunks*512; i += 256) {
        int c    = i >> 9;
        int j    = i & 511;
        int kpl  = j >> 5;              // local pair row 0..15
        int col0 = (j & 31) << 2;       // col quad base
        int kp   = c*16 + kpl;
        uint4 vh = *(const uint4*)(Wph + kp*128 + col0);
        uint4 vl = *(const uint4*)(Wpl + kp*128 + col0);
        int s = kpl >> 3, pp = kpl & 7, tig = pp & 3, reg = pp >> 2;
        int nt = col0 >> 3;
        int b0 = ((((nt<<1)+s)<<5) + ((col0 & 7)<<2) + tig);
        unsigned* wh = Wsh + c*2048;
        unsigned* wl = Wsl + c*2048;
        wh[(b0+0)*2+reg] = vh.x; wh[(b0+4)*2+reg] = vh.y;
        wh[(b0+8)*2+reg] = vh.z; wh[(b0+12)*2+reg] = vh.w;
        wl[(b0+0)*2+reg] = vl.x; wl[(b0+4)*2+reg] = vl.y;
        wl[(b0+8)*2+reg] = vl.z; wl[(b0+12)*2+reg] = vl.w;
    }

    // hoisted bias and stats registers (cols are tile-invariant)
    const int colq = (lane & 3) << 1;
    float bv[4][2];
#pragma unroll
    for (int ni = 0; ni < 4; ++ni) {
        int c = wn*32 + ni*8 + colq;
        bv[ni][0] = bias[c];
        bv[ni][1] = bias[c+1];
    }
    float cs[4][2], cq[4][2];
#pragma unroll
    for (int ni=0;ni<4;++ni){ cs[ni][0]=cs[ni][1]=0.f; cq[ni][0]=cq[ni][1]=0.f; }

    const int ntiles = (M + 127) >> 7;
    for (int tile = blockIdx.x; tile < ntiles; tile += gridDim.x) {
        const int m0 = tile << 7;

        float acc[4][4][4];
#pragma unroll
        for (int i=0;i<4;++i)
#pragma unroll
            for (int j=0;j<4;++j)
#pragma unroll
                for (int r=0;r<4;++r) acc[i][j][r] = 0.f;

        for (int ch = 0; ch < chunks; ++ch) {
            __syncthreads();
            // ---- stage A chunk ----
#pragma unroll
            for (int it = 0; it < 2; ++it) {
                int i2  = tid + it*256;
                int row = i2 >> 2, q = i2 & 3;
                int grow = m0 + row;
                uint4 vh = make_uint4(0,0,0,0), vl = make_uint4(0,0,0,0);
                if (FP32A) {
                    float4 u0 = make_float4(0.f,0.f,0.f,0.f), u1 = u0;
                    if (grow < M) {
                        const float* Afp = (const float*)Aop;
                        long off = (long)grow*ld + ch*32 + (q << 3);
                        u0 = *(const float4*)(Afp + off);
                        u1 = *(const float4*)(Afp + off + 4);
                        if (TRANSFORM) {
                            int gk = ch*32 + (q << 3);
                            float4 s0 = *(const float4*)(sc+gk), s1 = *(const float4*)(sc+gk+4);
                            float4 t0 = *(const float4*)(sh+gk), t1 = *(const float4*)(sh+gk+4);
                            u0.x = fmaxf(fmaf(u0.x,s0.x,t0.x),0.f);
                            u0.y = fmaxf(fmaf(u0.y,s0.y,t0.y),0.f);
                            u0.z = fmaxf(fmaf(u0.z,s0.z,t0.z),0.f);
                            u0.w = fmaxf(fmaf(u0.w,s0.w,t0.w),0.f);
                            u1.x = fmaxf(fmaf(u1.x,s1.x,t1.x),0.f);
                            u1.y = fmaxf(fmaf(u1.y,s1.y,t1.y),0.f);
                            u1.z = fmaxf(fmaf(u1.z,s1.z,t1.z),0.f);
                            u1.w = fmaxf(fmaf(u1.w,s1.w,t1.w),0.f);
                        }
                    }
                    split_pack(u0.x,u0.y, vh.x, vl.x);
                    split_pack(u0.z,u0.w, vh.y, vl.y);
                    split_pack(u1.x,u1.y, vh.z, vl.z);
                    split_pack(u1.z,u1.w, vh.w, vl.w);
                } else {
                    if (grow < M) {
                        const unsigned* Aph = (const unsigned*)Aop;
                        long off = (long)grow*ld + ch*16 + (q << 2);
                        vh = *(const uint4*)(Aph + off);
                        vl = *(const uint4*)(Apl + off);
                    }
                }
                int s  = q >> 1, ph = q & 1;
                int reg = ((row >> 3) & 1) | (ph << 1);
                int b0 = ((((row >> 4) << 1) + s) << 5) + ((row & 7) << 2);
                Ash[(b0+0)*4+reg] = vh.x; Ash[(b0+1)*4+reg] = vh.y;
                Ash[(b0+2)*4+reg] = vh.z; Ash[(b0+3)*4+reg] = vh.w;
                Asl[(b0+0)*4+reg] = vl.x; Asl[(b0+1)*4+reg] = vl.y;
                Asl[(b0+2)*4+reg] = vl.z; Asl[(b0+3)*4+reg] = vl.w;
            }
            __syncthreads();

            // ---- compute: 2 k16 steps, 4x4 warp tiles, bf16x3 ----
            const unsigned* wh = Wsh + ch*2048;
            const unsigned* wl = Wsl + ch*2048;
#pragma unroll
            for (int s = 0; s < 2; ++s) {
                unsigned bh[4][2], bl[4][2];
#pragma unroll
                for (int ni = 0; ni < 4; ++ni) {
                    int base = (((((wn*4 + ni) << 1) + s) << 5) | lane) << 1;
                    uint2 fh = *(const uint2*)&wh[base];
                    uint2 fl = *(const uint2*)&wl[base];
                    bh[ni][0]=fh.x; bh[ni][1]=fh.y;
                    bl[ni][0]=fl.x; bl[ni][1]=fl.y;
                }
#pragma unroll
                for (int mi = 0; mi < 4; ++mi) {
                    int base = (((((wm*4 + mi) << 1) + s) << 5) | lane) << 2;
                    uint4 ah = *(const uint4*)&Ash[base];
                    uint4 al = *(const uint4*)&Asl[base];
#pragma unroll
                    for (int ni = 0; ni < 4; ++ni) {
                        MMA_BF16(acc[mi][ni], ah.x, ah.y, ah.z, ah.w, bh[ni][0], bh[ni][1]);
                        MMA_BF16(acc[mi][ni], ah.x, ah.y, ah.z, ah.w, bl[ni][0], bl[ni][1]);
                        MMA_BF16(acc[mi][ni], al.x, al.y, al.z, al.w, bh[ni][0], bh[ni][1]);
                    }
                }
            }
        }

        // ---- epilogue ----
#pragma unroll
        for (int mi = 0; mi < 4; ++mi) {
#pragma unroll
            for (int half = 0; half < 2; ++half) {
                int row = m0 + wm*64 + mi*16 + (lane >> 2) + half*8;
                if (row < M) {
                    int sA = 0, dA = 0, e0i = 0, e1i = 0, e2i = 0;
                    if (EPI == 2) { sA = srcg[row]; dA = dstg[row]; }
                    if (EPI == 1) {
                        e0i = eint[row*3+0]; e1i = eint[row*3+1]; e2i = eint[row*3+2];
                    }
#pragma unroll
                    for (int ni = 0; ni < 4; ++ni) {
                        int c = wn*32 + ni*8 + colq;
                        float y0 = acc[mi][ni][half*2+0] + bv[ni][0];
                        float y1 = acc[mi][ni][half*2+1] + bv[ni][1];
                        if (EPI == 2) {
                            float2 x = *(const float2*)(Xsrc + (long)sA*128 + c);
                            float2 m;
                            m.x = fmaxf(x.x + y0, 0.f);
                            m.y = fmaxf(x.y + y1, 0.f);
#if defined(__CUDA_ARCH__) && (__CUDA_ARCH__ >= 900)
                            atomicAdd((float2*)(Pdst + (long)dA*128 + c), m);
#else
                            atomicAdd(Pdst + (long)dA*128 + c,     m.x);
                            atomicAdd(Pdst + (long)dA*128 + c + 1, m.y);
#endif
                        } else {
                            if (EPI == 1) {
                                float2 t0 = *(const float2*)(etab + (0*12 + e0i)*128 + c);
                                float2 t1 = *(const float2*)(etab + (1*12 + e1i)*128 + c);
                                float2 t2 = *(const float2*)(etab + (2*12 + e2i)*128 + c);
                                y0 += t0.x + t1.x + t2.x;
                                y1 += t0.y + t1.y + t2.y;
                            }
                            *(float2*)(Y + (long)row*128 + c) = make_float2(y0, y1);
                            if (STATS) {
                                cs[ni][0] += y0; cs[ni][1] += y1;
                                cq[ni][0] += y0*y0; cq[ni][1] += y1*y1;
                            }
                        }
                    }
                }
            }
        }
    }

    if (STATS) {
        __syncthreads();
#pragma unroll
        for (int ni = 0; ni < 4; ++ni) {
            int c = wn*32 + ni*8 + colq;
            atomicAdd(&sSum[c],   cs[ni][0]);
            atomicAdd(&sSum[c+1], cs[ni][1]);
            atomicAdd(&sSq[c],    cq[ni][0]);
            atomicAdd(&sSq[c+1],  cq[ni][1]);
        }
        __syncthreads();
        if (tid < 128) {
            atomicAdd(&stats[tid],     sSum[tid]);
            atomicAdd(&stats[128+tid], sSq[tid]);
        }
    }
}

// weight transpose+split: W[b][K][128] fp32 -> [b][kp][n] pair-packed
__global__ void k_splitW(const float* __restrict__ W, unsigned* __restrict__ dh,
                         unsigned* __restrict__ dl, int K, int Kp2, int total)
{
    int idx = blockIdx.x*blockDim.x + threadIdx.x;
    if (idx >= total) return;
    int b   = idx / (Kp2*128);
    int rem = idx - b*Kp2*128;
    int kp  = rem >> 7;
    int n   = rem & 127;
    int k0 = kp*2, k1 = k0 + 1;
    float v0 = (k0 < K) ? W[(long)b*K*128 + (long)k0*128 + n] : 0.f;
    float v1 = (k1 < K) ? W[(long)b*K*128 + (long)k1*128 + n] : 0.f;
    unsigned h, l;
    split_pack(v0, v1, h, l);
    dh[idx] = h; dl[idx] = l;
}

// ---------------- GIN helpers -----------------------------------------------
// P = (1+eps) * T(x), T = relu(bn) when TR else identity
template<bool TR>
__global__ void k_init_pre(const float4* __restrict__ X, float4* __restrict__ P,
                           int M32, const float* __restrict__ epsP,
                           const float* __restrict__ sc, const float* __restrict__ sh)
{
    int t = blockIdx.x*blockDim.x + threadIdx.x;
    if (t >= M32) return;
    float e = 1.f + *epsP;
    float4 x = X[t];
    if (TR) {
        int cb = (t & 31) << 2;
        x.x = fmaxf(fmaf(x.x, sc[cb+0], sh[cb+0]), 0.f);
        x.y = fmaxf(fmaf(x.y, sc[cb+1], sh[cb+1]), 0.f);
        x.z = fmaxf(fmaf(x.z, sc[cb+2], sh[cb+2]), 0.f);
        x.w = fmaxf(fmaf(x.w, sc[cb+3], sh[cb+3]), 0.f);
    }
    x.x *= e; x.y *= e; x.z *= e; x.w *= e;
    P[t] = x;
}

// atomicAdd(P[dst], relu(Tx(x[src]) + Te(ea)))
template<bool TR>
__global__ void k_scatter(const float4* __restrict__ X, const float4* __restrict__ EA,
                          const int* __restrict__ src, const int* __restrict__ dst,
                          float4* __restrict__ P, int E32,
                          const float* __restrict__ scx, const float* __restrict__ shx,
                          const float* __restrict__ sce, const float* __restrict__ she)
{
    int t = blockIdx.x*blockDim.x + threadIdx.x;
    if (t >= E32) return;
    int e = t >> 5, l = t & 31;
    int s = src[e], d = dst[e];
    float4 x = X[s*32 + l];
    float4 a = EA[(e<<5) + l];
    if (TR) {
        int cb = l << 2;
        x.x = fmaxf(fmaf(x.x, scx[cb+0], shx[cb+0]), 0.f);
        x.y = fmaxf(fmaf(x.y, scx[cb+1], shx[cb+1]), 0.f);
        x.z = fmaxf(fmaf(x.z, scx[cb+2], shx[cb+2]), 0.f);
        x.w = fmaxf(fmaf(x.w, scx[cb+3], shx[cb+3]), 0.f);
        a.x = fmaxf(fmaf(a.x, sce[cb+0], she[cb+0]), 0.f);
        a.y = fmaxf(fmaf(a.y, sce[cb+1], she[cb+1]), 0.f);
        a.z = fmaxf(fmaf(a.z, sce[cb+2], she[cb+2]), 0.f);
        a.w = fmaxf(fmaf(a.w, sce[cb+3], she[cb+3]), 0.f);
    }
    float4 m;
    m.x = fmaxf(x.x + a.x, 0.f);
    m.y = fmaxf(x.y + a.y, 0.f);
    m.z = fmaxf(x.z + a.z, 0.f);
    m.w = fmaxf(x.w + a.w, 0.f);
#if defined(__CUDA_ARCH__) && (__CUDA_ARCH__ >= 900)
    atomicAdd(&P[d*32 + l], m);
#else
    float* p = (float*)&P[d*32 + l];
    atomicAdd(p+0, m.x); atomicAdd(p+1, m.y);
    atomicAdd(p+2, m.z); atomicAdd(p+3, m.w);
#endif
}

__global__ void k_bn_finalize(float* __restrict__ stats, const float* __restrict__ g,
                              const float* __restrict__ b, float invM,
                              float* __restrict__ oscale, float* __restrict__ oshift)
{
    int c = threadIdx.x;   // 128
    float mu  = stats[c] * invM;
    float var = stats[128+c] * invM - mu*mu;
    float rs  = rsqrtf(var + 1e-5f);
    float scv = g[c] * rs;
    oscale[c] = scv;
    oshift[c] = b[c] - mu*scv;
    stats[c] = 0.f;
    stats[128+c] = 0.f;
}

// ---------------- embeddings ------------------------------------------------
__global__ void k_atom_embed(const int* __restrict__ xa, const float4* __restrict__ tab,
                             float4* __restrict__ H, int N32)
{
    int t = blockIdx.x*blockDim.x + threadIdx.x;
    if (t >= N32) return;
    int n = t >> 5, l = t & 31;
    float4 s = make_float4(0.f,0.f,0.f,0.f);
#pragma unroll
    for (int f=0; f<9; ++f) {
        int idx = xa[n*9 + f];
        float4 v = tab[(f*124 + idx)*32 + l];
        s.x += v.x; s.y += v.y; s.z += v.z; s.w += v.w;
    }
    H[t] = s;
}

__device__ __forceinline__ float bond_rbf_val(const float* xf, int e, int k)
{
    if (k >= 240) return 0.f;
    int f = k / 30, c = k % 30;
    if (c >= c_bf_cnt[f]) return 0.f;
    float x = xf[e*8 + f];
    float ctr = (float)(c_bf_start[f] + c_bf_step[f] * (double)c);
    float d = x - ctr;
    return expf(-c_bf_g[f] * d * d);
}

__global__ void k_rbf_bond(const float* __restrict__ xf,
                           unsigned* __restrict__ Ah, unsigned* __restrict__ Al)
{
    int e = blockIdx.x;
    int kp = threadIdx.x;   // 0..127 pairs (K=256)
    float v0 = bond_rbf_val(xf, e, 2*kp);
    float v1 = bond_rbf_val(xf, e, 2*kp + 1);
    unsigned h, l;
    split_pack(v0, v1, h, l);
    Ah[e*128 + kp] = h; Al[e*128 + kp] = l;
}

__device__ __forceinline__ float ang_val(const float* xa, int a, int k)
{
    if (k < 32) {
        float ctr = (float)((double)k * 0.1);
        float d = xa[a*6] - ctr;
        return expf(-10.f * d * d);
    } else if (k < 37) {
        return xa[a*6 + (k - 31)];
    }
    return 0.f;
}

__global__ void k_rbf_ang(const float* __restrict__ xa,
                          unsigned* __restrict__ Ah, unsigned* __restrict__ Al, int A)
{
    int idx = blockIdx.x*blockDim.x + threadIdx.x;
    int a = idx >> 5, kp = idx & 31;   // 32 pairs (K=64)
    if (a >= A) return;
    float v0 = ang_val(xa, a, 2*kp);
    float v1 = ang_val(xa, a, 2*kp + 1);
    unsigned h, l;
    split_pack(v0, v1, h, l);
    Ah[a*32 + kp] = h; Al[a*32 + kp] = l;
}

// pack angle weights [64,128] per layer (zero padded) and combined biases
__global__ void k_pack(const float* __restrict__ baWang, const float* __restrict__ baWrest,
                       const float* __restrict__ baBang, const float* __restrict__ baBrest,
                       const float* __restrict__ bfb,
                       float* __restrict__ Wang, float* __restrict__ bang,
                       float* __restrict__ bbond)
{
    int c = threadIdx.x;   // 128
    for (int l=0; l<LL; ++l) {
        for (int r=0; r<64; ++r) {
            float v = 0.f;
            if (r < 32)      v = baWang[(l*32 + r)*128 + c];
            else if (r < 37) v = baWrest[(l*5 + (r-32))*128 + c];
            Wang[(l*64 + r)*128 + c] = v;
        }
        bang[l*128 + c] = baBang[l*128 + c] + baBrest[l*128 + c];
    }
    for (int l=0; l<=LL; ++l) {
        float s = 0.f;
        for (int f=0; f<8; ++f) s += bfb[(l*8 + f)*128 + c];
        bbond[l*128 + c] = s;
    }
}

__global__ void k_copy_out(const float4* __restrict__ H, const float4* __restrict__ HB,
                           float4* __restrict__ O, int N32, int T32)
{
    int t = blockIdx.x*blockDim.x + threadIdx.x;
    if (t >= T32) return;
    O[t] = (t < N32) ? H[t] : HB[t - N32];
}

// ---------------- launcher ---------------------------------------------------
extern "C" void kernel_launch(void* const* d_in, const int* in_sizes, int n_in,
                              void* d_out, int out_size)
{
    const int N = NN, E = EE, A = AA;

    const int*   x_atom      = (const int*)  d_in[0];
    const int*   edge_index  = (const int*)  d_in[1];
    const int*   eint        = (const int*)  d_in[2];
    const int*   eiba        = (const int*)  d_in[3];
    const float* eaf         = (const float*)d_in[4];
    const float* eab         = (const float*)d_in[5];
    const float* atom_tables = (const float*)d_in[6];
    const float* bond_tables = (const float*)d_in[7];
    const float* bf_W        = (const float*)d_in[8];
    const float* bf_b        = (const float*)d_in[9];
    const float* ba_W_ang    = (const float*)d_in[10];
    const float* ba_b_ang    = (const float*)d_in[11];
    const float* ba_W_rest   = (const float*)d_in[12];
    const float* ba_b_rest   = (const float*)d_in[13];
    const float* eps_a       = (const float*)d_in[14];
    const float* W1_a        = (const float*)d_in[15];
    const float* b1_a        = (const float*)d_in[16];
    const float* bng_a       = (const float*)d_in[17];
    const float* bnb_a       = (const float*)d_in[18];
    const float* W2_a        = (const float*)d_in[19];
    const float* b2_a        = (const float*)d_in[20];
    const float* eps_g       = (const float*)d_in[21];
    const float* W1_g        = (const float*)d_in[22];
    const float* b1_g        = (const float*)d_in[23];
    const float* bng_g       = (const float*)d_in[24];
    const float* bnb_g       = (const float*)d_in[25];
    const float* W2_g        = (const float*)d_in[26];
    const float* b2_g        = (const float*)d_in[27];
    const float* obng_a      = (const float*)d_in[28];
    const float* obnb_a      = (const float*)d_in[29];
    const float* obng_ba     = (const float*)d_in[30];
    const float* obnb_ba     = (const float*)d_in[31];

    const int* src  = edge_index;
    const int* dst  = edge_index + E;
    const int* srcb = eiba;
    const int* dstb = eiba + A;

    float *ph, *phb, *ppre, *pt, *pembB;
    float *pWang, *pbang, *pbbond, *pstats, *pbns, *pbnsh;
    float *pobsAs, *pobsAh, *pobsBs, *pobsBh;
    unsigned *Abh,*Abl,*Aah,*Aal;
    unsigned *W1ah,*W1al,*W2ah,*W2al,*W1gh,*W1gl,*W2gh,*W2gl,*bfWh,*bfWl,*Wgah,*Wgal;
    cudaGetSymbolAddress((void**)&ph,    g_h);
    cudaGetSymbolAddress((void**)&phb,   g_hb);
    cudaGetSymbolAddress((void**)&ppre,  g_pre);
    cudaGetSymbolAddress((void**)&pt,    g_t);
    cudaGetSymbolAddress((void**)&pembB, g_embB);
    cudaGetSymbolAddress((void**)&pWang, g_Wang);
    cudaGetSymbolAddress((void**)&pbang, g_bang);
    cudaGetSymbolAddress((void**)&pbbond,g_bbond);
    cudaGetSymbolAddress((void**)&pstats,g_stats);
    cudaGetSymbolAddress((void**)&pbns,  g_bns);
    cudaGetSymbolAddress((void**)&pbnsh, g_bnsh);
    cudaGetSymbolAddress((void**)&pobsAs,g_obsAs);
    cudaGetSymbolAddress((void**)&pobsAh,g_obsAh);
    cudaGetSymbolAddress((void**)&pobsBs,g_obsBs);
    cudaGetSymbolAddress((void**)&pobsBh,g_obsBh);
    cudaGetSymbolAddress((void**)&Abh,   g_Abh);
    cudaGetSymbolAddress((void**)&Abl,   g_Abl);
    cudaGetSymbolAddress((void**)&Aah,   g_Aah);
    cudaGetSymbolAddress((void**)&Aal,   g_Aal);
    cudaGetSymbolAddress((void**)&W1ah,  g_W1ah); cudaGetSymbolAddress((void**)&W1al, g_W1al);
    cudaGetSymbolAddress((void**)&W2ah,  g_W2ah); cudaGetSymbolAddress((void**)&W2al, g_W2al);
    cudaGetSymbolAddress((void**)&W1gh,  g_W1gh); cudaGetSymbolAddress((void**)&W1gl, g_W1gl);
    cudaGetSymbolAddress((void**)&W2gh,  g_W2gh); cudaGetSymbolAddress((void**)&W2gl, g_W2gl);
    cudaGetSymbolAddress((void**)&bfWh,  g_bfWh); cudaGetSymbolAddress((void**)&bfWl, g_bfWl);
    cudaGetSymbolAddress((void**)&Wgah,  g_Wgah); cudaGetSymbolAddress((void**)&Wgal, g_Wgal);

    // dynamic smem opt-in (largest: chunks=8 -> 147456 B)
    cudaFuncSetAttribute(gemm_ps<false,false,false,1>, cudaFuncAttributeMaxDynamicSharedMemorySize, 147456);
    cudaFuncSetAttribute(gemm_ps<false,false,false,2>, cudaFuncAttributeMaxDynamicSharedMemorySize, 147456);
    cudaFuncSetAttribute(gemm_ps<true,false,true,0>,   cudaFuncAttributeMaxDynamicSharedMemorySize, 147456);
    cudaFuncSetAttribute(gemm_ps<true,true,true,0>,    cudaFuncAttributeMaxDynamicSharedMemorySize, 147456);
    cudaFuncSetAttribute(gemm_ps<true,true,false,0>,   cudaFuncAttributeMaxDynamicSharedMemorySize, 147456);

    auto blks = [](int n){ return (n + 255) / 256; };
    auto dynB = [](int chunks){ return (2*chunks + 2) * 2048 * 4; };
    auto gsz  = [](int M){ int t = (M+127)/128; return t < 148 ? t : 148; };

    // --- one-time (per call) precompute ---
    k_pack<<<1,128>>>(ba_W_ang, ba_W_rest, ba_b_ang, ba_b_rest, bf_b,
                      pWang, pbang, pbbond);
    k_splitW<<<blks(LL*64*128),256>>>(W1_a, W1ah, W1al, 128, 64, LL*64*128);
    k_splitW<<<blks(LL*64*128),256>>>(W2_a, W2ah, W2al, 128, 64, LL*64*128);
    k_splitW<<<blks(LL*64*128),256>>>(W1_g, W1gh, W1gl, 128, 64, LL*64*128);
    k_splitW<<<blks(LL*64*128),256>>>(W2_g, W2gh, W2gl, 128, 64, LL*64*128);
    k_splitW<<<blks((LL+1)*128*128),256>>>(bf_W, bfWh, bfWl, 240, 128, (LL+1)*128*128);
    k_splitW<<<blks(LL*32*128),256>>>(pWang, Wgah, Wgal, 64, 32, LL*32*128);
    k_rbf_bond<<<E, 128>>>(eaf, Abh, Abl);
    k_rbf_ang<<<blks(A*32),256>>>(eab, Aah, Aal, A);

    // --- initial embeddings ---
    k_atom_embed<<<blks(N*32),256>>>(x_atom, (const float4*)atom_tables, (float4*)ph, N*32);
    // phb = int-embed (fused epilogue) + rbf@bfW + bias
    gemm_ps<false,false,false,1><<<gsz(E),256,dynB(8)>>>(
        Abh, Abl, 128, 8, bfWh, bfWl, pbbond, phb, E,
        nullptr, nullptr, nullptr, nullptr, nullptr, nullptr, nullptr,
        eint, bond_tables);

    for (int l = 0; l < LL; ++l) {
        const bool last = (l == LL - 1);

        // ===== atom GIN conv =====
        if (l == 0) {
            k_init_pre<false><<<blks(N*32),256>>>((const float4*)ph, (float4*)ppre, N*32,
                                                  eps_a + l, nullptr, nullptr);
            k_scatter<false><<<blks(E*32),256>>>((const float4*)ph, (const float4*)phb,
                src, dst, (float4*)ppre, E*32, nullptr, nullptr, nullptr, nullptr);
        } else {
            k_init_pre<true><<<blks(N*32),256>>>((const float4*)ph, (float4*)ppre, N*32,
                                                 eps_a + l, pobsAs, pobsAh);
            k_scatter<true><<<blks(E*32),256>>>((const float4*)ph, (const float4*)phb,
                src, dst, (float4*)ppre, E*32, pobsAs, pobsAh, pobsBs, pobsBh);
        }
        gemm_ps<true,false,true,0><<<gsz(N),256,dynB(4)>>>(
            ppre, nullptr, 128, 4, W1ah + l*8192, W1al + l*8192, b1_a + l*128, pt, N,
            pstats, nullptr, nullptr, nullptr, nullptr, nullptr, nullptr, nullptr, nullptr);
        k_bn_finalize<<<1,128>>>(pstats, bng_a + l*128, bnb_a + l*128, 1.0f/N, pbns, pbnsh);
        if (!last) {
            gemm_ps<true,true,true,0><<<gsz(N),256,dynB(4)>>>(
                pt, nullptr, 128, 4, W2ah + l*8192, W2al + l*8192, b2_a + l*128, ph, N,
                pstats, pbns, pbnsh, nullptr, nullptr, nullptr, nullptr, nullptr, nullptr);
            k_bn_finalize<<<1,128>>>(pstats, obng_a + l*128, obnb_a + l*128, 1.0f/N,
                                     pobsAs, pobsAh);
        } else {
            gemm_ps<true,true,false,0><<<gsz(N),256,dynB(4)>>>(
                pt, nullptr, 128, 4, W2ah + l*8192, W2al + l*8192, b2_a + l*128, ph, N,
                nullptr, pbns, pbnsh, nullptr, nullptr, nullptr, nullptr, nullptr, nullptr);
        }

        // ===== bond embeddings for layer l+1 (int-embed fused in epilogue) =====
        gemm_ps<false,false,false,1><<<gsz(E),256,dynB(8)>>>(
            Abh, Abl, 128, 8, bfWh + (l+1)*16384, bfWl + (l+1)*16384,
            pbbond + (l+1)*128, pembB, E,
            nullptr, nullptr, nullptr, nullptr, nullptr, nullptr, nullptr,
            eint, bond_tables + (l+1)*3*12*128);

        // ===== bond GIN conv =====
        k_init_pre<false><<<blks(E*32),256>>>((const float4*)pembB, (float4*)ppre, E*32,
                                              eps_g + l, nullptr, nullptr);
        // angle embed GEMM + fused scatter into ppre
        gemm_ps<false,false,false,2><<<gsz(A),256,dynB(2)>>>(
            Aah, Aal, 32, 2, Wgah + l*4096, Wgal + l*4096, pbang + l*128, nullptr, A,
            nullptr, nullptr, nullptr, srcb, dstb, pembB, ppre, nullptr, nullptr);
        gemm_ps<true,false,true,0><<<gsz(E),256,dynB(4)>>>(
            ppre, nullptr, 128, 4, W1gh + l*8192, W1gl + l*8192, b1_g + l*128, pt, E,
            pstats, nullptr, nullptr, nullptr, nullptr, nullptr, nullptr, nullptr, nullptr);
        k_bn_finalize<<<1,128>>>(pstats, bng_g + l*128, bnb_g + l*128, 1.0f/E, pbns, pbnsh);
        if (!last) {
            gemm_ps<true,true,true,0><<<gsz(E),256,dynB(4)>>>(
                pt, nullptr, 128, 4, W2gh + l*8192, W2gl + l*8192, b2_g + l*128, phb, E,
                pstats, pbns, pbnsh, nullptr, nullptr, nullptr, nullptr, nullptr, nullptr);
            k_bn_finalize<<<1,128>>>(pstats, obng_ba + l*128, obnb_ba + l*128, 1.0f/E,
                                     pobsBs, pobsBh);
        } else {
            gemm_ps<true,true,false,0><<<gsz(E),256,dynB(4)>>>(
                pt, nullptr, 128, 4, W2gh + l*8192, W2gl + l*8192, b2_g + l*128, phb, E,
                nullptr, pbns, pbnsh, nullptr, nullptr, nullptr, nullptr, nullptr, nullptr);
        }
    }

    // --- output: [h (N*128) ; h_ba (E*128)] ---
    int T32 = (N + E) * 32;
    k_copy_out<<<blks(T32),256>>>((const float4*)ph, (const float4*)phb,
                                  (float4*)d_out, N*32, T32);
}

// round 7
// speedup vs baseline: 1.6611x; 1.1858x over previous
#include <cuda_runtime.h>
#include <cuda_bf16.h>
#include <math.h>

#define NN 100000
#define EE 200000
#define AA 400000
#define LL 5

// ---------------- scratch (static device globals; no runtime alloc) ----------
__device__ float g_h[NN*128];
__device__ float g_hb[EE*128];
__device__ float g_pre[EE*128];
__device__ float g_t[EE*128];
__device__ float g_embB[EE*128];

__device__ unsigned g_Abh[EE*128], g_Abl[EE*128];   // bond RBF basis (128 pairs)
__device__ unsigned g_Aah[AA*32],  g_Aal[AA*32];    // angle basis (32 pairs)
__device__ unsigned g_W1ah[LL*64*128], g_W1al[LL*64*128];
__device__ unsigned g_W2ah[LL*64*128], g_W2al[LL*64*128];
__device__ unsigned g_W1gh[LL*64*128], g_W1gl[LL*64*128];
__device__ unsigned g_W2gh[LL*64*128], g_W2gl[LL*64*128];
__device__ unsigned g_bfWh[(LL+1)*128*128], g_bfWl[(LL+1)*128*128];
__device__ unsigned g_Wgah[LL*32*128],  g_Wgal[LL*32*128];

__device__ float g_Wang[LL*64*128];
__device__ float g_bang[LL*128];
__device__ float g_bbond[(LL+1)*128];
__device__ float g_zero[128];          // stays 0 (never written)
__device__ float g_stats[256];
__device__ float g_bns[128];
__device__ float g_bnsh[128];
__device__ float g_obsAs[128], g_obsAh[128];
__device__ float g_obsBs[128], g_obsBh[128];

__constant__ double c_bf_start[8] = {0.0,0.0,3.0,0.0,0.0,0.0,0.0,0.0};
__constant__ double c_bf_step[8]  = {0.1,0.05,0.3,0.05,0.05,0.05,0.5,0.05};
__constant__ int    c_bf_cnt[8]   = {20,20,30,20,20,20,20,20};
__constant__ float  c_bf_g[8]     = {10.f,1.f,1.f,1.f,1.f,1.f,2.f,1.f};

// ---------------- helpers -----------------------------------------------------
__device__ __forceinline__ void split_pack(float x, float y, unsigned &hi, unsigned &lo)
{
    __nv_bfloat16 bx = __float2bfloat16_rn(x);
    __nv_bfloat16 by = __float2bfloat16_rn(y);
    float rx = x - __bfloat162float(bx);
    float ry = y - __bfloat162float(by);
    __nv_bfloat16 brx = __float2bfloat16_rn(rx);
    __nv_bfloat16 bry = __float2bfloat16_rn(ry);
    hi = ((unsigned)__bfloat16_as_ushort(by) << 16) | __bfloat16_as_ushort(bx);
    lo = ((unsigned)__bfloat16_as_ushort(bry) << 16) | __bfloat16_as_ushort(brx);
}

#define MMA_BF16(d, a0,a1,a2,a3, b0,b1) \
    asm volatile( \
        "mma.sync.aligned.m16n8k16.row.col.f32.bf16.bf16.f32 " \
        "{%0,%1,%2,%3}, {%4,%5,%6,%7}, {%8,%9}, {%0,%1,%2,%3};" \
        : "+f"(d[0]), "+f"(d[1]), "+f"(d[2]), "+f"(d[3]) \
        : "r"(a0), "r"(a1), "r"(a2), "r"(a3), "r"(b0), "r"(b1))

// ---------------- persistent bf16x3 mma GEMM (pipelined, 2 CTA/SM) -----------
// Y[M,128] = A[M,K] @ W^T + bias
//  FP32A: A fp32 (split in staging); else pre-split pair-packed (ld in pairs).
//  TRANSFORM (FP32A): relu(bn()) on A load. STATS: fused col sum/sumsq.
//  EPI: 0 plain store; 1 store + int-embed gather add; 2 scatter(relu(X[src]+y))
//  ACCUM: Y += result (EPI 0/1 only).
template<bool FP32A, bool TRANSFORM, bool STATS, int EPI, bool ACCUM>
__global__ void __launch_bounds__(256,2) gemm_ps(
    const void* __restrict__ Aop, const unsigned* __restrict__ Apl, int ld, int chunks,
    const unsigned* __restrict__ Wph, const unsigned* __restrict__ Wpl,
    const float* __restrict__ bias, float* __restrict__ Y, int M,
    float* __restrict__ stats, const float* __restrict__ sc, const float* __restrict__ sh,
    const int* __restrict__ srcg, const int* __restrict__ dstg,
    const float* __restrict__ Xsrc, float* __restrict__ Pdst,
    const int* __restrict__ eint, const float* __restrict__ etab)
{
    extern __shared__ unsigned dyn[];
    unsigned* Wsh   = dyn;
    unsigned* Wsl   = dyn + chunks*2048;
    unsigned* Abase = dyn + 2*chunks*2048;   // 2 buffers x (2048 hi + 2048 lo)
    __shared__ float sSum[128], sSq[128];

    const int tid  = threadIdx.x;
    const int lane = tid & 31;
    const int warp = tid >> 5;
    const int wm = warp >> 2;
    const int wn = warp & 3;

    if (STATS && tid < 128) { sSum[tid] = 0.f; sSq[tid] = 0.f; }

    // ---- stage W once ----
    for (int i = tid; i < chunks*512; i += 256) {
        int c    = i >> 9;
        int j    = i & 511;
        int kpl  = j >> 5;
        int col0 = (j & 31) << 2;
        int kp   = c*16 + kpl;
        uint4 vh = *(const uint4*)(Wph + kp*128 + col0);
        uint4 vl = *(const uint4*)(Wpl + kp*128 + col0);
        int s = kpl >> 3, pp = kpl & 7, tig = pp & 3, reg = pp >> 2;
        int nt = col0 >> 3;
        int b0 = ((((nt<<1)+s)<<5) + ((col0 & 7)<<2) + tig);
        unsigned* wh = Wsh + c*2048;
        unsigned* wl = Wsl + c*2048;
        wh[(b0+0)*2+reg] = vh.x; wh[(b0+4)*2+reg] = vh.y;
        wh[(b0+8)*2+reg] = vh.z; wh[(b0+12)*2+reg] = vh.w;
        wl[(b0+0)*2+reg] = vl.x; wl[(b0+4)*2+reg] = vl.y;
        wl[(b0+8)*2+reg] = vl.z; wl[(b0+12)*2+reg] = vl.w;
    }

    const int colq = (lane & 3) << 1;
    float bv[4][2];
#pragma unroll
    for (int ni = 0; ni < 4; ++ni) {
        int c = wn*32 + ni*8 + colq;
        bv[ni][0] = bias[c];
        bv[ni][1] = bias[c+1];
    }
    float cs[4][2], cq[4][2];
#pragma unroll
    for (int ni=0;ni<4;++ni){ cs[ni][0]=cs[ni][1]=0.f; cq[ni][0]=cq[ni][1]=0.f; }

    // per-thread staging geometry (row/q fixed across chunks)
    const int row0 = tid >> 2,        q0 = tid & 3;
    const int row1 = (tid+256) >> 2,  q1 = (tid+256) & 3;

    // prefetch registers
    float4 pf[2][2];
    uint4  pvh[2], pvl[2];

    const int ntiles = (M + 127) >> 7;
    for (int tile = blockIdx.x; tile < ntiles; tile += gridDim.x) {
        const int m0 = tile << 7;

        float acc[4][4][4];
#pragma unroll
        for (int i=0;i<4;++i)
#pragma unroll
            for (int j=0;j<4;++j)
#pragma unroll
                for (int r=0;r<4;++r) acc[i][j][r] = 0.f;

        // ---- load_chunk(c) into registers ----
        auto load_chunk = [&](int c) {
#pragma unroll
            for (int it = 0; it < 2; ++it) {
                int row = it ? row1 : row0, q = it ? q1 : q0;
                int grow = m0 + row;
                if (FP32A) {
                    pf[it][0] = make_float4(0.f,0.f,0.f,0.f);
                    pf[it][1] = pf[it][0];
                    if (grow < M) {
                        const float* Afp = (const float*)Aop;
                        long off = (long)grow*ld + c*32 + (q << 3);
                        pf[it][0] = *(const float4*)(Afp + off);
                        pf[it][1] = *(const float4*)(Afp + off + 4);
                    }
                } else {
                    pvh[it] = make_uint4(0,0,0,0);
                    pvl[it] = make_uint4(0,0,0,0);
                    if (grow < M) {
                        const unsigned* Aph = (const unsigned*)Aop;
                        long off = (long)grow*ld + c*16 + (q << 2);
                        pvh[it] = *(const uint4*)(Aph + off);
                        pvl[it] = *(const uint4*)(Apl + off);
                    }
                }
            }
        };
        // ---- store_chunk(c): convert (if fp32) + write smem buffer c&1 ----
        auto store_chunk = [&](int c) {
            unsigned* Ash = Abase + (c & 1)*4096;
            unsigned* Asl = Ash + 2048;
#pragma unroll
            for (int it = 0; it < 2; ++it) {
                int row = it ? row1 : row0, q = it ? q1 : q0;
                uint4 vh, vl;
                if (FP32A) {
                    float4 u0 = pf[it][0], u1 = pf[it][1];
                    if (TRANSFORM) {
                        int gk = c*32 + (q << 3);
                        float4 s0 = *(const float4*)(sc+gk), s1 = *(const float4*)(sc+gk+4);
                        float4 t0 = *(const float4*)(sh+gk), t1 = *(const float4*)(sh+gk+4);
                        u0.x = fmaxf(fmaf(u0.x,s0.x,t0.x),0.f);
                        u0.y = fmaxf(fmaf(u0.y,s0.y,t0.y),0.f);
                        u0.z = fmaxf(fmaf(u0.z,s0.z,t0.z),0.f);
                        u0.w = fmaxf(fmaf(u0.w,s0.w,t0.w),0.f);
                        u1.x = fmaxf(fmaf(u1.x,s1.x,t1.x),0.f);
                        u1.y = fmaxf(fmaf(u1.y,s1.y,t1.y),0.f);
                        u1.z = fmaxf(fmaf(u1.z,s1.z,t1.z),0.f);
                        u1.w = fmaxf(fmaf(u1.w,s1.w,t1.w),0.f);
                    }
                    split_pack(u0.x,u0.y, vh.x, vl.x);
                    split_pack(u0.z,u0.w, vh.y, vl.y);
                    split_pack(u1.x,u1.y, vh.z, vl.z);
                    split_pack(u1.z,u1.w, vh.w, vl.w);
                } else {
                    vh = pvh[it]; vl = pvl[it];
                }
                int s  = q >> 1, ph = q & 1;
                int reg = ((row >> 3) & 1) | (ph << 1);
                int b0 = ((((row >> 4) << 1) + s) << 5) + ((row & 7) << 2);
                Ash[(b0+0)*4+reg] = vh.x; Ash[(b0+1)*4+reg] = vh.y;
                Ash[(b0+2)*4+reg] = vh.z; Ash[(b0+3)*4+reg] = vh.w;
                Asl[(b0+0)*4+reg] = vl.x; Asl[(b0+1)*4+reg] = vl.y;
                Asl[(b0+2)*4+reg] = vl.z; Asl[(b0+3)*4+reg] = vl.w;
            }
        };

        // prologue: chunk 0
        load_chunk(0);
        store_chunk(0);
        __syncthreads();

        for (int ch = 0; ch < chunks; ++ch) {
            if (ch + 1 < chunks) load_chunk(ch + 1);

            // ---- compute chunk ch from buffer ch&1 ----
            const unsigned* Ash = Abase + (ch & 1)*4096;
            const unsigned* Asl = Ash + 2048;
            const unsigned* wh = Wsh + ch*2048;
            const unsigned* wl = Wsl + ch*2048;
#pragma unroll
            for (int s = 0; s < 2; ++s) {
                unsigned bh[4][2], bl[4][2];
#pragma unroll
                for (int ni = 0; ni < 4; ++ni) {
                    int base = (((((wn*4 + ni) << 1) + s) << 5) | lane) << 1;
                    uint2 fh = *(const uint2*)&wh[base];
                    uint2 fl = *(const uint2*)&wl[base];
                    bh[ni][0]=fh.x; bh[ni][1]=fh.y;
                    bl[ni][0]=fl.x; bl[ni][1]=fl.y;
                }
#pragma unroll
                for (int mi = 0; mi < 4; ++mi) {
                    int base = (((((wm*4 + mi) << 1) + s) << 5) | lane) << 2;
                    uint4 ah = *(const uint4*)&Ash[base];
                    uint4 al = *(const uint4*)&Asl[base];
#pragma unroll
                    for (int ni = 0; ni < 4; ++ni) {
                        MMA_BF16(acc[mi][ni], ah.x, ah.y, ah.z, ah.w, bh[ni][0], bh[ni][1]);
                        MMA_BF16(acc[mi][ni], ah.x, ah.y, ah.z, ah.w, bl[ni][0], bl[ni][1]);
                        MMA_BF16(acc[mi][ni], al.x, al.y, al.z, al.w, bh[ni][0], bh[ni][1]);
                    }
                }
            }

            if (ch + 1 < chunks) {
                store_chunk(ch + 1);
                __syncthreads();
            }
        }

        // ---- epilogue ----
#pragma unroll
        for (int mi = 0; mi < 4; ++mi) {
#pragma unroll
            for (int half = 0; half < 2; ++half) {
                int row = m0 + wm*64 + mi*16 + (lane >> 2) + half*8;
                if (row < M) {
                    int sA = 0, dA = 0, e0i = 0, e1i = 0, e2i = 0;
                    if (EPI == 2) { sA = srcg[row]; dA = dstg[row]; }
                    if (EPI == 1) {
                        e0i = eint[row*3+0]; e1i = eint[row*3+1]; e2i = eint[row*3+2];
                    }
#pragma unroll
                    for (int ni = 0; ni < 4; ++ni) {
                        int c = wn*32 + ni*8 + colq;
                        float y0 = acc[mi][ni][half*2+0] + bv[ni][0];
                        float y1 = acc[mi][ni][half*2+1] + bv[ni][1];
                        if (EPI == 2) {
                            float2 x = *(const float2*)(Xsrc + (long)sA*128 + c);
                            float2 m;
                            m.x = fmaxf(x.x + y0, 0.f);
                            m.y = fmaxf(x.y + y1, 0.f);
#if defined(__CUDA_ARCH__) && (__CUDA_ARCH__ >= 900)
                            atomicAdd((float2*)(Pdst + (long)dA*128 + c), m);
#else
                            atomicAdd(Pdst + (long)dA*128 + c,     m.x);
                            atomicAdd(Pdst + (long)dA*128 + c + 1, m.y);
#endif
                        } else {
                            if (EPI == 1) {
                                float2 t0 = *(const float2*)(etab + (0*12 + e0i)*128 + c);
                                float2 t1 = *(const float2*)(etab + (1*12 + e1i)*128 + c);
                                float2 t2 = *(const float2*)(etab + (2*12 + e2i)*128 + c);
                                y0 += t0.x + t1.x + t2.x;
                                y1 += t0.y + t1.y + t2.y;
                            }
                            float* yp = Y + (long)row*128 + c;
                            if (ACCUM) {
                                float2 p = *(const float2*)yp;
                                y0 += p.x; y1 += p.y;
                            }
                            *(float2*)yp = make_float2(y0, y1);
                            if (STATS) {
                                cs[ni][0] += y0; cs[ni][1] += y1;
                                cq[ni][0] += y0*y0; cq[ni][1] += y1*y1;
                            }
                        }
                    }
                }
            }
        }
    }

    if (STATS) {
        __syncthreads();
#pragma unroll
        for (int ni = 0; ni < 4; ++ni) {
            int c = wn*32 + ni*8 + colq;
            atomicAdd(&sSum[c],   cs[ni][0]);
            atomicAdd(&sSum[c+1], cs[ni][1]);
            atomicAdd(&sSq[c],    cq[ni][0]);
            atomicAdd(&sSq[c+1],  cq[ni][1]);
        }
        __syncthreads();
        if (tid < 128) {
            atomicAdd(&stats[tid],     sSum[tid]);
            atomicAdd(&stats[128+tid], sSq[tid]);
        }
    }
}

// weight transpose+split: W[b][K][128] fp32 -> [b][kp][n] pair-packed
__global__ void k_splitW(const float* __restrict__ W, unsigned* __restrict__ dh,
                         unsigned* __restrict__ dl, int K, int Kp2, int total)
{
    int idx = blockIdx.x*blockDim.x + threadIdx.x;
    if (idx >= total) return;
    int b   = idx / (Kp2*128);
    int rem = idx - b*Kp2*128;
    int kp  = rem >> 7;
    int n   = rem & 127;
    int k0 = kp*2, k1 = k0 + 1;
    float v0 = (k0 < K) ? W[(long)b*K*128 + (long)k0*128 + n] : 0.f;
    float v1 = (k1 < K) ? W[(long)b*K*128 + (long)k1*128 + n] : 0.f;
    unsigned h, l;
    split_pack(v0, v1, h, l);
    dh[idx] = h; dl[idx] = l;
}

// ---------------- GIN helpers -----------------------------------------------
template<bool TR>
__global__ void k_init_pre(const float4* __restrict__ X, float4* __restrict__ P,
                           int M32, const float* __restrict__ epsP,
                           const float* __restrict__ sc, const float* __restrict__ sh)
{
    int t = blockIdx.x*blockDim.x + threadIdx.x;
    if (t >= M32) return;
    float e = 1.f + *epsP;
    float4 x = X[t];
    if (TR) {
        int cb = (t & 31) << 2;
        x.x = fmaxf(fmaf(x.x, sc[cb+0], sh[cb+0]), 0.f);
        x.y = fmaxf(fmaf(x.y, sc[cb+1], sh[cb+1]), 0.f);
        x.z = fmaxf(fmaf(x.z, sc[cb+2], sh[cb+2]), 0.f);
        x.w = fmaxf(fmaf(x.w, sc[cb+3], sh[cb+3]), 0.f);
    }
    x.x *= e; x.y *= e; x.z *= e; x.w *= e;
    P[t] = x;
}

template<bool TR>
__global__ void k_scatter(const float4* __restrict__ X, const float4* __restrict__ EA,
                          const int* __restrict__ src, const int* __restrict__ dst,
                          float4* __restrict__ P, int E32,
                          const float* __restrict__ scx, const float* __restrict__ shx,
                          const float* __restrict__ sce, const float* __restrict__ she)
{
    int t = blockIdx.x*blockDim.x + threadIdx.x;
    if (t >= E32) return;
    int e = t >> 5, l = t & 31;
    int s = src[e], d = dst[e];
    float4 x = X[s*32 + l];
    float4 a = EA[(e<<5) + l];
    if (TR) {
        int cb = l << 2;
        x.x = fmaxf(fmaf(x.x, scx[cb+0], shx[cb+0]), 0.f);
        x.y = fmaxf(fmaf(x.y, scx[cb+1], shx[cb+1]), 0.f);
        x.z = fmaxf(fmaf(x.z, scx[cb+2], shx[cb+2]), 0.f);
        x.w = fmaxf(fmaf(x.w, scx[cb+3], shx[cb+3]), 0.f);
        a.x = fmaxf(fmaf(a.x, sce[cb+0], she[cb+0]), 0.f);
        a.y = fmaxf(fmaf(a.y, sce[cb+1], she[cb+1]), 0.f);
        a.z = fmaxf(fmaf(a.z, sce[cb+2], she[cb+2]), 0.f);
        a.w = fmaxf(fmaf(a.w, sce[cb+3], she[cb+3]), 0.f);
    }
    float4 m;
    m.x = fmaxf(x.x + a.x, 0.f);
    m.y = fmaxf(x.y + a.y, 0.f);
    m.z = fmaxf(x.z + a.z, 0.f);
    m.w = fmaxf(x.w + a.w, 0.f);
#if defined(__CUDA_ARCH__) && (__CUDA_ARCH__ >= 900)
    atomicAdd(&P[d*32 + l], m);
#else
    float* p = (float*)&P[d*32 + l];
    atomicAdd(p+0, m.x); atomicAdd(p+1, m.y);
    atomicAdd(p+2, m.z); atomicAdd(p+3, m.w);
#endif
}

__global__ void k_bn_finalize(float* __restrict__ stats, const float* __restrict__ g,
                              const float* __restrict__ b, float invM,
                              float* __restrict__ oscale, float* __restrict__ oshift)
{
    int c = threadIdx.x;
    float mu  = stats[c] * invM;
    float var = stats[128+c] * invM - mu*mu;
    float rs  = rsqrtf(var + 1e-5f);
    float scv = g[c] * rs;
    oscale[c] = scv;
    oshift[c] = b[c] - mu*scv;
    stats[c] = 0.f;
    stats[128+c] = 0.f;
}

// ---------------- embeddings ------------------------------------------------
__global__ void k_atom_embed(const int* __restrict__ xa, const float4* __restrict__ tab,
                             float4* __restrict__ H, int N32)
{
    int t = blockIdx.x*blockDim.x + threadIdx.x;
    if (t >= N32) return;
    int n = t >> 5, l = t & 31;
    float4 s = make_float4(0.f,0.f,0.f,0.f);
#pragma unroll
    for (int f=0; f<9; ++f) {
        int idx = xa[n*9 + f];
        float4 v = tab[(f*124 + idx)*32 + l];
        s.x += v.x; s.y += v.y; s.z += v.z; s.w += v.w;
    }
    H[t] = s;
}

__device__ __forceinline__ float bond_rbf_val(const float* xf, int e, int k)
{
    if (k >= 240) return 0.f;
    int f = k / 30, c = k % 30;
    if (c >= c_bf_cnt[f]) return 0.f;
    float x = xf[e*8 + f];
    float ctr = (float)(c_bf_start[f] + c_bf_step[f] * (double)c);
    float d = x - ctr;
    return expf(-c_bf_g[f] * d * d);
}

__global__ void k_rbf_bond(const float* __restrict__ xf,
                           unsigned* __restrict__ Ah, unsigned* __restrict__ Al)
{
    int e = blockIdx.x;
    int kp = threadIdx.x;
    float v0 = bond_rbf_val(xf, e, 2*kp);
    float v1 = bond_rbf_val(xf, e, 2*kp + 1);
    unsigned h, l;
    split_pack(v0, v1, h, l);
    Ah[e*128 + kp] = h; Al[e*128 + kp] = l;
}

__device__ __forceinline__ float ang_val(const float* xa, int a, int k)
{
    if (k < 32) {
        float ctr = (float)((double)k * 0.1);
        float d = xa[a*6] - ctr;
        return expf(-10.f * d * d);
    } else if (k < 37) {
        return xa[a*6 + (k - 31)];
    }
    return 0.f;
}

__global__ void k_rbf_ang(const float* __restrict__ xa,
                          unsigned* __restrict__ Ah, unsigned* __restrict__ Al, int A)
{
    int idx = blockIdx.x*blockDim.x + threadIdx.x;
    int a = idx >> 5, kp = idx & 31;
    if (a >= A) return;
    float v0 = ang_val(xa, a, 2*kp);
    float v1 = ang_val(xa, a, 2*kp + 1);
    unsigned h, l;
    split_pack(v0, v1, h, l);
    Ah[a*32 + kp] = h; Al[a*32 + kp] = l;
}

__global__ void k_pack(const float* __restrict__ baWang, const float* __restrict__ baWrest,
                       const float* __restrict__ baBang, const float* __restrict__ baBrest,
                       const float* __restrict__ bfb,
                       float* __restrict__ Wang, float* __restrict__ bang,
                       float* __restrict__ bbond)
{
    int c = threadIdx.x;
    for (int l=0; l<LL; ++l) {
        for (int r=0; r<64; ++r) {
            float v = 0.f;
            if (r < 32)      v = baWang[(l*32 + r)*128 + c];
            else if (r < 37) v = baWrest[(l*5 + (r-32))*128 + c];
            Wang[(l*64 + r)*128 + c] = v;
        }
        bang[l*128 + c] = baBang[l*128 + c] + baBrest[l*128 + c];
    }
    for (int l=0; l<=LL; ++l) {
        float s = 0.f;
        for (int f=0; f<8; ++f) s += bfb[(l*8 + f)*128 + c];
        bbond[l*128 + c] = s;
    }
}

__global__ void k_copy_out(const float4* __restrict__ H, const float4* __restrict__ HB,
                           float4* __restrict__ O, int N32, int T32)
{
    int t = blockIdx.x*blockDim.x + threadIdx.x;
    if (t >= T32) return;
    O[t] = (t < N32) ? H[t] : HB[t - N32];
}

// ---------------- launcher ---------------------------------------------------
extern "C" void kernel_launch(void* const* d_in, const int* in_sizes, int n_in,
                              void* d_out, int out_size)
{
    const int N = NN, E = EE, A = AA;

    const int*   x_atom      = (const int*)  d_in[0];
    const int*   edge_index  = (const int*)  d_in[1];
    const int*   eint        = (const int*)  d_in[2];
    const int*   eiba        = (const int*)  d_in[3];
    const float* eaf         = (const float*)d_in[4];
    const float* eab         = (const float*)d_in[5];
    const float* atom_tables = (const float*)d_in[6];
    const float* bond_tables = (const float*)d_in[7];
    const float* bf_W        = (const float*)d_in[8];
    const float* bf_b        = (const float*)d_in[9];
    const float* ba_W_ang    = (const float*)d_in[10];
    const float* ba_b_ang    = (const float*)d_in[11];
    const float* ba_W_rest   = (const float*)d_in[12];
    const float* ba_b_rest   = (const float*)d_in[13];
    const float* eps_a       = (const float*)d_in[14];
    const float* W1_a        = (const float*)d_in[15];
    const float* b1_a        = (const float*)d_in[16];
    const float* bng_a       = (const float*)d_in[17];
    const float* bnb_a       = (const float*)d_in[18];
    const float* W2_a        = (const float*)d_in[19];
    const float* b2_a        = (const float*)d_in[20];
    const float* eps_g       = (const float*)d_in[21];
    const float* W1_g        = (const float*)d_in[22];
    const float* b1_g        = (const float*)d_in[23];
    const float* bng_g       = (const float*)d_in[24];
    const float* bnb_g       = (const float*)d_in[25];
    const float* W2_g        = (const float*)d_in[26];
    const float* b2_g        = (const float*)d_in[27];
    const float* obng_a      = (const float*)d_in[28];
    const float* obnb_a      = (const float*)d_in[29];
    const float* obng_ba     = (const float*)d_in[30];
    const float* obnb_ba     = (const float*)d_in[31];

    const int* src  = edge_index;
    const int* dst  = edge_index + E;
    const int* srcb = eiba;
    const int* dstb = eiba + A;

    float *ph, *phb, *ppre, *pt, *pembB;
    float *pWang, *pbang, *pbbond, *pzero, *pstats, *pbns, *pbnsh;
    float *pobsAs, *pobsAh, *pobsBs, *pobsBh;
    unsigned *Abh,*Abl,*Aah,*Aal;
    unsigned *W1ah,*W1al,*W2ah,*W2al,*W1gh,*W1gl,*W2gh,*W2gl,*bfWh,*bfWl,*Wgah,*Wgal;
    cudaGetSymbolAddress((void**)&ph,    g_h);
    cudaGetSymbolAddress((void**)&phb,   g_hb);
    cudaGetSymbolAddress((void**)&ppre,  g_pre);
    cudaGetSymbolAddress((void**)&pt,    g_t);
    cudaGetSymbolAddress((void**)&pembB, g_embB);
    cudaGetSymbolAddress((void**)&pWang, g_Wang);
    cudaGetSymbolAddress((void**)&pbang, g_bang);
    cudaGetSymbolAddress((void**)&pbbond,g_bbond);
    cudaGetSymbolAddress((void**)&pzero, g_zero);
    cudaGetSymbolAddress((void**)&pstats,g_stats);
    cudaGetSymbolAddress((void**)&pbns,  g_bns);
    cudaGetSymbolAddress((void**)&pbnsh, g_bnsh);
    cudaGetSymbolAddress((void**)&pobsAs,g_obsAs);
    cudaGetSymbolAddress((void**)&pobsAh,g_obsAh);
    cudaGetSymbolAddress((void**)&pobsBs,g_obsBs);
    cudaGetSymbolAddress((void**)&pobsBh,g_obsBh);
    cudaGetSymbolAddress((void**)&Abh,   g_Abh);
    cudaGetSymbolAddress((void**)&Abl,   g_Abl);
    cudaGetSymbolAddress((void**)&Aah,   g_Aah);
    cudaGetSymbolAddress((void**)&Aal,   g_Aal);
    cudaGetSymbolAddress((void**)&W1ah,  g_W1ah); cudaGetSymbolAddress((void**)&W1al, g_W1al);
    cudaGetSymbolAddress((void**)&W2ah,  g_W2ah); cudaGetSymbolAddress((void**)&W2al, g_W2al);
    cudaGetSymbolAddress((void**)&W1gh,  g_W1gh); cudaGetSymbolAddress((void**)&W1gl, g_W1gl);
    cudaGetSymbolAddress((void**)&W2gh,  g_W2gh); cudaGetSymbolAddress((void**)&W2gl, g_W2gl);
    cudaGetSymbolAddress((void**)&bfWh,  g_bfWh); cudaGetSymbolAddress((void**)&bfWl, g_bfWl);
    cudaGetSymbolAddress((void**)&Wgah,  g_Wgah); cudaGetSymbolAddress((void**)&Wgal, g_Wgal);

    // smem: chunks*16KB (W) + 32KB (A double buffer); max chunks=4 -> 96KB
    cudaFuncSetAttribute(gemm_ps<false,false,false,0,false>, cudaFuncAttributeMaxDynamicSharedMemorySize, 98304);
    cudaFuncSetAttribute(gemm_ps<false,false,false,1,true>,  cudaFuncAttributeMaxDynamicSharedMemorySize, 98304);
    cudaFuncSetAttribute(gemm_ps<false,false,false,2,false>, cudaFuncAttributeMaxDynamicSharedMemorySize, 98304);
    cudaFuncSetAttribute(gemm_ps<true,false,true,0,false>,   cudaFuncAttributeMaxDynamicSharedMemorySize, 98304);
    cudaFuncSetAttribute(gemm_ps<true,true,true,0,false>,    cudaFuncAttributeMaxDynamicSharedMemorySize, 98304);
    cudaFuncSetAttribute(gemm_ps<true,true,false,0,false>,   cudaFuncAttributeMaxDynamicSharedMemorySize, 98304);

    auto blks = [](int n){ return (n + 255) / 256; };
    auto dynB = [](int chunks){ return chunks*16384 + 32768; };
    auto gsz  = [](int M){ int t = (M+127)/128; return t < 296 ? t : 296; };

    // --- one-time (per call) precompute ---
    k_pack<<<1,128>>>(ba_W_ang, ba_W_rest, ba_b_ang, ba_b_rest, bf_b,
                      pWang, pbang, pbbond);
    k_splitW<<<blks(LL*64*128),256>>>(W1_a, W1ah, W1al, 128, 64, LL*64*128);
    k_splitW<<<blks(LL*64*128),256>>>(W2_a, W2ah, W2al, 128, 64, LL*64*128);
    k_splitW<<<blks(LL*64*128),256>>>(W1_g, W1gh, W1gl, 128, 64, LL*64*128);
    k_splitW<<<blks(LL*64*128),256>>>(W2_g, W2gh, W2gl, 128, 64, LL*64*128);
    k_splitW<<<blks((LL+1)*128*128),256>>>(bf_W, bfWh, bfWl, 240, 128, (LL+1)*128*128);
    k_splitW<<<blks(LL*32*128),256>>>(pWang, Wgah, Wgal, 64, 32, LL*32*128);
    k_rbf_bond<<<E, 128>>>(eaf, Abh, Abl);
    k_rbf_ang<<<blks(A*32),256>>>(eab, Aah, Aal, A);

    // bond-float embed = two K=128 halves: first writes (bias), second accum + int-embed
    auto bond_embed = [&](int l, float* out) {
        gemm_ps<false,false,false,0,false><<<gsz(E),256,dynB(4)>>>(
            Abh, Abl, 128, 4, bfWh + l*16384, bfWl + l*16384,
            pbbond + l*128, out, E,
            nullptr, nullptr, nullptr, nullptr, nullptr, nullptr, nullptr,
            nullptr, nullptr);
        gemm_ps<false,false,false,1,true><<<gsz(E),256,dynB(4)>>>(
            Abh + 64, Abl + 64, 128, 4, bfWh + l*16384 + 8192, bfWl + l*16384 + 8192,
            pzero, out, E,
            nullptr, nullptr, nullptr, nullptr, nullptr, nullptr, nullptr,
            eint, bond_tables + (long)l*3*12*128);
    };

    // --- initial embeddings ---
    k_atom_embed<<<blks(N*32),256>>>(x_atom, (const float4*)atom_tables, (float4*)ph, N*32);
    bond_embed(0, phb);

    for (int l = 0; l < LL; ++l) {
        const bool last = (l == LL - 1);

        // ===== atom GIN conv =====
        if (l == 0) {
            k_init_pre<false><<<blks(N*32),256>>>((const float4*)ph, (float4*)ppre, N*32,
                                                  eps_a + l, nullptr, nullptr);
            k_scatter<false><<<blks(E*32),256>>>((const float4*)ph, (const float4*)phb,
                src, dst, (float4*)ppre, E*32, nullptr, nullptr, nullptr, nullptr);
        } else {
            k_init_pre<true><<<blks(N*32),256>>>((const float4*)ph, (float4*)ppre, N*32,
                                                 eps_a + l, pobsAs, pobsAh);
            k_scatter<true><<<blks(E*32),256>>>((const float4*)ph, (const float4*)phb,
                src, dst, (float4*)ppre, E*32, pobsAs, pobsAh, pobsBs, pobsBh);
        }
        gemm_ps<true,false,true,0,false><<<gsz(N),256,dynB(4)>>>(
            ppre, nullptr, 128, 4, W1ah + l*8192, W1al + l*8192, b1_a + l*128, pt, N,
            pstats, nullptr, nullptr, nullptr, nullptr, nullptr, nullptr, nullptr, nullptr);
        k_bn_finalize<<<1,128>>>(pstats, bng_a + l*128, bnb_a + l*128, 1.0f/N, pbns, pbnsh);
        if (!last) {
            gemm_ps<true,true,true,0,false><<<gsz(N),256,dynB(4)>>>(
                pt, nullptr, 128, 4, W2ah + l*8192, W2al + l*8192, b2_a + l*128, ph, N,
                pstats, pbns, pbnsh, nullptr, nullptr, nullptr, nullptr, nullptr, nullptr);
            k_bn_finalize<<<1,128>>>(pstats, obng_a + l*128, obnb_a + l*128, 1.0f/N,
                                     pobsAs, pobsAh);
        } else {
            gemm_ps<true,true,false,0,false><<<gsz(N),256,dynB(4)>>>(
                pt, nullptr, 128, 4, W2ah + l*8192, W2al + l*8192, b2_a + l*128, ph, N,
                nullptr, pbns, pbnsh, nullptr, nullptr, nullptr, nullptr, nullptr, nullptr);
        }

        // ===== bond embeddings for layer l+1 =====
        bond_embed(l + 1, pembB);

        // ===== bond GIN conv =====
        k_init_pre<false><<<blks(E*32),256>>>((const float4*)pembB, (float4*)ppre, E*32,
                                              eps_g + l, nullptr, nullptr);
        gemm_ps<false,false,false,2,false><<<gsz(A),256,dynB(2)>>>(
            Aah, Aal, 32, 2, Wgah + l*4096, Wgal + l*4096, pbang + l*128, nullptr, A,
            nullptr, nullptr, nullptr, srcb, dstb, pembB, ppre, nullptr, nullptr);
        gemm_ps<true,false,true,0,false><<<gsz(E),256,dynB(4)>>>(
            ppre, nullptr, 128, 4, W1gh + l*8192, W1gl + l*8192, b1_g + l*128, pt, E,
            pstats, nullptr, nullptr, nullptr, nullptr, nullptr, nullptr, nullptr, nullptr);
        k_bn_finalize<<<1,128>>>(pstats, bng_g + l*128, bnb_g + l*128, 1.0f/E, pbns, pbnsh);
        if (!last) {
            gemm_ps<true,true,true,0,false><<<gsz(E),256,dynB(4)>>>(
                pt, nullptr, 128, 4, W2gh + l*8192, W2gl + l*8192, b2_g + l*128, phb, E,
                pstats, pbns, pbnsh, nullptr, nullptr, nullptr, nullptr, nullptr, nullptr);
            k_bn_finalize<<<1,128>>>(pstats, obng_ba + l*128, obnb_ba + l*128, 1.0f/E,
                                     pobsBs, pobsBh);
        } else {
            gemm_ps<true,true,false,0,false><<<gsz(E),256,dynB(4)>>>(
                pt, nullptr, 128, 4, W2gh + l*8192, W2gl + l*8192, b2_g + l*128, phb, E,
                nullptr, pbns, pbnsh, nullptr, nullptr, nullptr, nullptr, nullptr, nullptr);
        }
    }

    // --- output: [h (N*128) ; h_ba (E*128)] ---
    int T32 = (N + E) * 32;
    k_copy_out<<<blks(T32),256>>>((const float4*)ph, (const float4*)phb,
                                  (float4*)d_out, N*32, T32);
}